// round 7
// baseline (speedup 1.0000x reference)
#include <cuda_runtime.h>
#include <math.h>
#include <stdint.h>

// ---- problem constants ----
#define NWIN 98
#define NH 3
#define HD 32
#define CD 96
#define DD 16
#define HH 112
#define WW2 112
#define NWX 2048
#define BATCH 2
#define BTOT (BATCH*NWX)      // 4096
#define MTOT (BTOT*NWIN)      // 401408
#define LTOT (DD*HH*WW2)      // 200704
#define SCALE 0.17677669529663689f

// ---- scratch ----
__device__ float g_q[(size_t)BTOT*NH*NWIN*HD];   // (b_,h,n,hd), q pre-scaled
__device__ float g_k[(size_t)BTOT*NH*NWIN*HD];
__device__ float g_v[(size_t)BTOT*NH*NWIN*HD];
__device__ unsigned g_y[(size_t)MTOT*CD];        // tf32 bits (scattered spatial)
__device__ float g_bm[8*NH*NWIN*NWIN];           // bias+mask per (class, head)
__device__ unsigned g_Bp[5*9216];                // prepacked B frags

// ---- tf32 helpers ----
__device__ __forceinline__ unsigned f2tf(float x) {
    unsigned r;
    asm("cvt.rna.tf32.f32 %0, %1;" : "=r"(r) : "f"(x));
    return r;
}
__device__ __forceinline__ void mma_tf32(float* d, uint4 a, uint2 b) {
    asm volatile(
        "mma.sync.aligned.m16n8k8.row.col.f32.tf32.tf32.f32 "
        "{%0,%1,%2,%3}, {%4,%5,%6,%7}, {%8,%9}, {%0,%1,%2,%3};"
        : "+f"(d[0]), "+f"(d[1]), "+f"(d[2]), "+f"(d[3])
        : "r"(a.x), "r"(a.y), "r"(a.z), "r"(a.w), "r"(b.x), "r"(b.y));
}

// ============ K0a: combined bias+mask table ============
__global__ void bm_kernel(const float* __restrict__ table,
                          const float* __restrict__ mask) {
    int idx = blockIdx.x * blockDim.x + threadIdx.x;
    if (idx >= 8 * NH * NWIN * NWIN) return;
    int cls = idx / (NH * NWIN * NWIN);
    int rem = idx % (NH * NWIN * NWIN);
    int head = rem / (NWIN * NWIN);
    int r = rem % (NWIN * NWIN);
    int n = r / NWIN, m = r % NWIN;
    int d1 = n / 49, h1 = (n % 49) / 7, w1 = n % 7;
    int d2 = m / 49, h2 = (m % 49) / 7, w2 = m % 7;
    int t = (d1 - d2 + 1) * 169 + (h1 - h2 + 6) * 13 + (w1 - w2 + 6);
    int wd = (cls & 4) ? 7 : 0;
    int wh = (cls & 2) ? 15 : 0;
    int ww = (cls & 1) ? 15 : 0;
    int widx = wd * 256 + wh * 16 + ww;
    g_bm[idx] = table[t * NH + head] + mask[(size_t)widx * (NWIN * NWIN) + r];
}

// ============ K0b: prepack weights into MMA B-fragment layout ============
__global__ void prepack_kernel(const float* __restrict__ qkvw,
                               const float* __restrict__ projw,
                               const float* __restrict__ fc1w) {
    int idx = blockIdx.x * blockDim.x + threadIdx.x;
    if (idx >= 5 * 9216) return;
    int mat = idx / 9216, rem = idx % 9216;
    int c = rem / 96, k = rem % 96;
    float v;
    if (mat < 3) v = qkvw[(size_t)(mat * 96 + c) * 96 + k];
    else if (mat == 3) v = projw[(size_t)c * 96 + k];
    else v = fc1w[(size_t)c * 96 + k];
    int word = (((c >> 3) * 12 + (k >> 3)) * 32 + (c & 7) * 4 + (k & 3)) * 2 + ((k >> 2) & 1);
    g_Bp[mat * 9216 + word] = f2tf(v);
}

// ============ GEMM common ============
#define GEMM_SMEM ((12800 + 9216) * 4)

__device__ __forceinline__ void mma12(float d[12][4], const unsigned* sAu,
                                      const unsigned* sB, int r0, int tig, int lane) {
    const uint2* b2 = (const uint2*)sB;
    #pragma unroll
    for (int kt = 0; kt < 12; kt++) {
        uint4 af;
        af.x = sAu[r0 * 100 + kt * 8 + tig];
        af.y = sAu[(r0 + 8) * 100 + kt * 8 + tig];
        af.z = sAu[r0 * 100 + kt * 8 + tig + 4];
        af.w = sAu[(r0 + 8) * 100 + kt * 8 + tig + 4];
        #pragma unroll
        for (int nt = 0; nt < 12; nt++) {
            uint2 bf = b2[(nt * 12 + kt) * 32 + lane];
            mma_tf32(d[nt], af, bf);
        }
    }
}

// ============ K1: fused LayerNorm + window-partition + QKV GEMM ============
__global__ __launch_bounds__(256, 2)
void gemm_qkv(const float* __restrict__ x,
              const float* __restrict__ nw,
              const float* __restrict__ nb,
              const float* __restrict__ bias) {
    extern __shared__ unsigned smu[];
    unsigned* sAu = smu;          // [128][100] tf32 bits
    unsigned* sB  = smu + 12800;
    int rowbase = blockIdx.x * 128;
    int tid = threadIdx.x;
    int w = tid >> 5, lane = tid & 31;
    int g = lane >> 2, tig = lane & 3;

    float nw0 = nw[lane], nw1 = nw[lane + 32], nw2 = nw[lane + 64];
    float nb0 = nb[lane], nb1 = nb[lane + 32], nb2 = nb[lane + 64];

    // ---- phase A: gather (shift+window) + LayerNorm -> sAu ----
    for (int i = 0; i < 16; i++) {
        int r = w * 16 + i;
        int m = rowbase + r;
        int b_ = m / NWIN, n = m % NWIN;
        int b = b_ >> 11;
        int widx = b_ & (NWX - 1);
        int wd = widx >> 8, wh = (widx >> 4) & 15, ww = widx & 15;
        int nd = n / 49, nr = n % 49, nh2 = nr / 7, nw2i = nr % 7;
        int dp = wd * 2 + nd, hp = wh * 7 + nh2, wp = ww * 7 + nw2i;
        int d = dp + 1; if (d >= DD) d -= DD;
        int h = hp + 3; if (h >= HH) h -= HH;
        int wq = wp + 3; if (wq >= WW2) wq -= WW2;
        size_t src = ((size_t)b * LTOT + (size_t)(d * (HH * WW2) + h * WW2 + wq)) * CD;
        float v0 = x[src + lane], v1 = x[src + 32 + lane], v2 = x[src + 64 + lane];
        float s = v0 + v1 + v2;
        float ss = v0 * v0 + v1 * v1 + v2 * v2;
        #pragma unroll
        for (int o = 16; o; o >>= 1) {
            s  += __shfl_xor_sync(0xffffffffu, s, o);
            ss += __shfl_xor_sync(0xffffffffu, ss, o);
        }
        float mean = s * (1.0f / 96.0f);
        float var = ss * (1.0f / 96.0f) - mean * mean;
        float rs = rsqrtf(var + 1e-5f);
        sAu[r * 100 + lane]      = f2tf((v0 - mean) * rs * nw0 + nb0);
        sAu[r * 100 + lane + 32] = f2tf((v1 - mean) * rs * nw1 + nb1);
        sAu[r * 100 + lane + 64] = f2tf((v2 - mean) * rs * nw2 + nb2);
    }

    int m0 = rowbase + w * 16 + g;
    int b0 = m0 / NWIN, n0 = m0 % NWIN;
    int b1 = (m0 + 8) / NWIN, n1 = (m0 + 8) % NWIN;
    int r0 = w * 16 + g;
    __syncthreads();

    // ---- phase B: loop q/k/v weight parts ----
    for (int p = 0; p < 3; p++) {
        if (p > 0) __syncthreads();
        {
            const uint4* s4 = (const uint4*)(g_Bp + p * 9216);
            uint4* d4 = (uint4*)sB;
            #pragma unroll
            for (int i = 0; i < 9; i++) d4[tid + i * 256] = s4[tid + i * 256];
        }
        __syncthreads();
        float d[12][4];
        #pragma unroll
        for (int nt = 0; nt < 12; nt++)
            #pragma unroll
            for (int r = 0; r < 4; r++) d[nt][r] = 0.0f;
        mma12(d, sAu, sB, r0, tig, lane);

        float* dstbuf = (p == 0) ? g_q : (p == 1) ? g_k : g_v;
        float sc = (p == 0) ? SCALE : 1.0f;
        #pragma unroll
        for (int nt = 0; nt < 12; nt++) {
            int c = nt * 8 + tig * 2;
            int head = c >> 5, wd = c & 31;
            float bx = bias[p * 96 + c], by = bias[p * 96 + c + 1];
            float2 v0 = make_float2((d[nt][0] + bx) * sc, (d[nt][1] + by) * sc);
            float2 v1 = make_float2((d[nt][2] + bx) * sc, (d[nt][3] + by) * sc);
            *(float2*)(dstbuf + ((((size_t)b0 * NH + head) * NWIN + n0) * HD + wd)) = v0;
            *(float2*)(dstbuf + ((((size_t)b1 * NH + head) * NWIN + n1) * HD + wd)) = v1;
        }
    }
}

// ============ K2: fused attention (3 heads) + proj, one CTA per window ============
// smem (u32 words):
//   q_u [112][36] = 4032 @ 0
//   k_u [104][36] = 3744 @ 4032
//   Ss  [98][108] = 10584 @ 0      (overlays q/k each head)
//   vT  [32][108] = 3456 @ 10584
//   Oacc[112][100]= 11200 @ 14040  (tf32 bits, proj A-tile)
//   sB (proj frags, 9216) overlays Ss region after last head
// total 25240 words = 100960 B -> 2 CTAs/SM
#define AP_SMEM (25240 * 4)
__global__ __launch_bounds__(224, 2)
void attn_proj_kernel(const float* __restrict__ projb) {
    extern __shared__ unsigned smu[];
    unsigned* q_u = smu;
    unsigned* k_u = smu + 4032;
    float* Ss = (float*)smu;
    unsigned* vT = smu + 10584;
    unsigned* Oacc = smu + 14040;
    unsigned* sB = smu;

    int b_ = blockIdx.x;
    int tid = threadIdx.x;
    int w = tid >> 5, lane = tid & 31;
    int g = lane >> 2, tig = lane & 3;
    int r0 = w * 16 + g;
    bool val0 = r0 < 98, val1 = (r0 + 8) < 98;

    // zero Oacc pad rows 98..111
    for (int i = tid; i < 14 * 100; i += 224) Oacc[9800 + i] = 0u;

    int widx = b_ & (NWX - 1);
    int cls = (((widx >> 8) == 7) << 2) | ((((widx >> 4) & 15) == 15) << 1) |
              ((widx & 15) == 15);

    for (int h = 0; h < NH; h++) {
        if (h) __syncthreads();   // prior PV reads of Ss/vT done before overwrite
        size_t base = ((size_t)b_ * NH + h) * (size_t)(NWIN * HD);

        // ---- load q/k/v, tf32-convert, plain-layout store ----
        {
            const float4* q4 = (const float4*)(g_q + base);
            const float4* k4 = (const float4*)(g_k + base);
            const float4* v4 = (const float4*)(g_v + base);
            for (int i4 = tid; i4 < 832; i4 += 224) {
                int n = i4 >> 3;
                int c = (i4 & 7) << 2;
                if (n < 98) {
                    float4 qv = q4[i4];
                    float4 kv = k4[i4];
                    float4 vv = v4[i4];
                    *(uint4*)(q_u + n * 36 + c) =
                        make_uint4(f2tf(qv.x), f2tf(qv.y), f2tf(qv.z), f2tf(qv.w));
                    *(uint4*)(k_u + n * 36 + c) =
                        make_uint4(f2tf(kv.x), f2tf(kv.y), f2tf(kv.z), f2tf(kv.w));
                    vT[(c + 0) * 108 + n] = f2tf(vv.x);
                    vT[(c + 1) * 108 + n] = f2tf(vv.y);
                    vT[(c + 2) * 108 + n] = f2tf(vv.z);
                    vT[(c + 3) * 108 + n] = f2tf(vv.w);
                } else {
                    vT[(c + 0) * 108 + n] = 0u;
                    vT[(c + 1) * 108 + n] = 0u;
                    vT[(c + 2) * 108 + n] = 0u;
                    vT[(c + 3) * 108 + n] = 0u;
                }
            }
        }
        __syncthreads();

        // ---- S = Q K^T ----
        float d[13][4];
        #pragma unroll
        for (int nt = 0; nt < 13; nt++)
            #pragma unroll
            for (int r = 0; r < 4; r++) d[nt][r] = 0.0f;
        {
            uint4 af[4];
            #pragma unroll
            for (int kt = 0; kt < 4; kt++) {
                af[kt].x = q_u[r0 * 36 + kt * 8 + tig];
                af[kt].y = q_u[(r0 + 8) * 36 + kt * 8 + tig];
                af[kt].z = q_u[r0 * 36 + kt * 8 + tig + 4];
                af[kt].w = q_u[(r0 + 8) * 36 + kt * 8 + tig + 4];
            }
            #pragma unroll
            for (int nt = 0; nt < 13; nt++) {
                #pragma unroll
                for (int kt = 0; kt < 4; kt++) {
                    uint2 bf;
                    bf.x = k_u[(nt * 8 + g) * 36 + kt * 8 + tig];
                    bf.y = k_u[(nt * 8 + g) * 36 + kt * 8 + tig + 4];
                    mma_tf32(d[nt], af[kt], bf);
                }
            }
        }
        __syncthreads();   // q/k reads done; region becomes Ss

        // ---- bias/mask + exp + row-sum in registers ----
        {
            const float* bmp = g_bm + (size_t)(cls * NH + h) * (NWIN * NWIN);
            float s0 = 0.0f, s1 = 0.0f;
            #pragma unroll
            for (int nt = 0; nt < 13; nt++) {
                int c0 = nt * 8 + tig * 2;
                float e0 = 0.f, e1 = 0.f, e2 = 0.f, e3 = 0.f;
                if (c0 < 98) {
                    if (val0) {
                        float2 bb = __ldg((const float2*)(bmp + r0 * 98 + c0));
                        e0 = __expf(d[nt][0] + bb.x);
                        e1 = __expf(d[nt][1] + bb.y);
                    }
                    if (val1) {
                        float2 bb = __ldg((const float2*)(bmp + (r0 + 8) * 98 + c0));
                        e2 = __expf(d[nt][2] + bb.x);
                        e3 = __expf(d[nt][3] + bb.y);
                    }
                }
                d[nt][0] = e0; d[nt][1] = e1; d[nt][2] = e2; d[nt][3] = e3;
                s0 += e0 + e1; s1 += e2 + e3;
            }
            s0 += __shfl_xor_sync(0xffffffffu, s0, 1);
            s0 += __shfl_xor_sync(0xffffffffu, s0, 2);
            s1 += __shfl_xor_sync(0xffffffffu, s1, 1);
            s1 += __shfl_xor_sync(0xffffffffu, s1, 2);
            float i0 = val0 ? (1.0f / s0) : 0.0f;
            float i1 = val1 ? (1.0f / s1) : 0.0f;
            #pragma unroll
            for (int nt = 0; nt < 13; nt++) {
                int c0 = nt * 8 + tig * 2;
                if (val0) *(float2*)(Ss + r0 * 108 + c0) =
                    make_float2(d[nt][0] * i0, d[nt][1] * i0);
                if (val1) *(float2*)(Ss + (r0 + 8) * 108 + c0) =
                    make_float2(d[nt][2] * i1, d[nt][3] * i1);
            }
        }
        __syncthreads();

        // ---- O = P V -> Oacc (tf32 bits) ----
        {
            int rA = val0 ? r0 : 0;
            int rB = val1 ? (r0 + 8) : 0;
            unsigned mA = val0 ? 0xffffffffu : 0u;
            unsigned mB = val1 ? 0xffffffffu : 0u;
            float o[4][4];
            #pragma unroll
            for (int nt = 0; nt < 4; nt++)
                #pragma unroll
                for (int r = 0; r < 4; r++) o[nt][r] = 0.0f;
            #pragma unroll
            for (int kt = 0; kt < 13; kt++) {
                uint4 af;
                af.x = f2tf(Ss[rA * 108 + kt * 8 + tig]) & mA;
                af.y = f2tf(Ss[rB * 108 + kt * 8 + tig]) & mB;
                af.z = f2tf(Ss[rA * 108 + kt * 8 + tig + 4]) & mA;
                af.w = f2tf(Ss[rB * 108 + kt * 8 + tig + 4]) & mB;
                #pragma unroll
                for (int nt = 0; nt < 4; nt++) {
                    uint2 bf;
                    bf.x = vT[(nt * 8 + g) * 108 + kt * 8 + tig];
                    bf.y = vT[(nt * 8 + g) * 108 + kt * 8 + tig + 4];
                    mma_tf32(o[nt], af, bf);
                }
            }
            #pragma unroll
            for (int nt = 0; nt < 4; nt++) {
                int c = h * 32 + nt * 8 + tig * 2;
                if (val0) *(uint2*)(Oacc + r0 * 100 + c) =
                    make_uint2(f2tf(o[nt][0]), f2tf(o[nt][1]));
                if (val1) *(uint2*)(Oacc + (r0 + 8) * 100 + c) =
                    make_uint2(f2tf(o[nt][2]), f2tf(o[nt][3]));
            }
        }
    }
    __syncthreads();   // all PV reads done; Ss region becomes sB

    // ---- copy proj weight fragments ----
    {
        const uint4* s4 = (const uint4*)(g_Bp + 3 * 9216);
        uint4* d4 = (uint4*)sB;
        for (int i = tid; i < 2304; i += 224) d4[i] = s4[i];
    }
    __syncthreads();

    // ---- proj GEMM + window-reverse scatter ----
    {
        float d[12][4];
        #pragma unroll
        for (int nt = 0; nt < 12; nt++)
            #pragma unroll
            for (int r = 0; r < 4; r++) d[nt][r] = 0.0f;
        mma12(d, Oacc, sB, r0, tig, lane);

        int b = b_ >> 11;
        int wd = widx >> 8, wh = (widx >> 4) & 15, ww = widx & 15;
        size_t rowdst[2];
        #pragma unroll
        for (int rr = 0; rr < 2; rr++) {
            int n = r0 + rr * 8;
            if (n >= 98) n = 0;    // dummy (store guarded)
            int nd = n / 49, nr = n % 49, nh2 = nr / 7, nw2 = nr % 7;
            int dp = wd * 2 + nd, hp = wh * 7 + nh2, wp = ww * 7 + nw2;
            int dd = dp + 1; if (dd >= DD) dd -= DD;
            int hh = hp + 3; if (hh >= HH) hh -= HH;
            int ww3 = wp + 3; if (ww3 >= WW2) ww3 -= WW2;
            rowdst[rr] = ((size_t)b * LTOT +
                          (size_t)(dd * (HH * WW2) + hh * WW2 + ww3)) * CD;
        }
        #pragma unroll
        for (int nt = 0; nt < 12; nt++) {
            int c = nt * 8 + tig * 2;
            float bx = projb[c], by = projb[c + 1];
            if (val0) *(uint2*)(g_y + rowdst[0] + c) =
                make_uint2(f2tf(d[nt][0] + bx), f2tf(d[nt][1] + by));
            if (val1) *(uint2*)(g_y + rowdst[1] + c) =
                make_uint2(f2tf(d[nt][2] + bx), f2tf(d[nt][3] + by));
        }
    }
}

// ============ K3: fc1 GEMM + GELU + residual ============
__global__ __launch_bounds__(256, 2)
void gemm_fc1(const float* __restrict__ bias,
              const float* __restrict__ resid,
              float* __restrict__ out) {
    extern __shared__ unsigned smu[];
    unsigned* sAu = smu;
    unsigned* sB  = smu + 12800;
    int rowbase = blockIdx.x * 128;
    int tid = threadIdx.x;
    int w = tid >> 5, lane = tid & 31;
    int g = lane >> 2, tig = lane & 3;
    int r0 = w * 16 + g;

    {
        const uint4* A4 = (const uint4*)(g_y + (size_t)rowbase * 96);
        #pragma unroll
        for (int it = 0; it < 12; it++) {
            int idx = tid + it * 256;
            int r = idx / 24, k4 = idx % 24;
            *(uint4*)(sAu + r * 100 + k4 * 4) = A4[idx];
        }
    }
    {
        const uint4* s4 = (const uint4*)(g_Bp + 4 * 9216);
        uint4* d4 = (uint4*)sB;
        #pragma unroll
        for (int i = 0; i < 9; i++) d4[tid + i * 256] = s4[tid + i * 256];
    }
    __syncthreads();

    float d[12][4];
    #pragma unroll
    for (int nt = 0; nt < 12; nt++)
        #pragma unroll
        for (int r = 0; r < 4; r++) d[nt][r] = 0.0f;
    mma12(d, sAu, sB, r0, tig, lane);

    int m0 = rowbase + r0;
    #pragma unroll
    for (int nt = 0; nt < 12; nt++) {
        int c = nt * 8 + tig * 2;
        float bx = bias[c], by = bias[c + 1];
        #pragma unroll
        for (int rr = 0; rr < 2; rr++) {
            size_t o = (size_t)(m0 + rr * 8) * CD + c;
            float v0 = d[nt][rr * 2] + bx;
            float v1 = d[nt][rr * 2 + 1] + by;
            float g0 = 0.5f * v0 * (1.0f + erff(v0 * 0.70710678118654752f));
            float g1 = 0.5f * v1 * (1.0f + erff(v1 * 0.70710678118654752f));
            float2 rv = *(const float2*)(resid + o);
            *(float2*)(out + o) = make_float2(rv.x + g0, rv.y + g1);
        }
    }
}

// ============ launch ============
extern "C" void kernel_launch(void* const* d_in, const int* in_sizes, int n_in,
                              void* d_out, int out_size) {
    const float* x     = (const float*)d_in[0];
    const float* mask  = (const float*)d_in[1];
    const float* n1w   = (const float*)d_in[2];
    const float* n1b   = (const float*)d_in[3];
    const float* qkvw  = (const float*)d_in[4];
    const float* qkvb  = (const float*)d_in[5];
    const float* relt  = (const float*)d_in[6];
    const float* projw = (const float*)d_in[7];
    const float* projb = (const float*)d_in[8];
    const float* fc1w  = (const float*)d_in[9];
    const float* fc1b  = (const float*)d_in[10];
    float* out = (float*)d_out;

    cudaFuncSetAttribute(attn_proj_kernel, cudaFuncAttributeMaxDynamicSharedMemorySize, AP_SMEM);
    cudaFuncSetAttribute(gemm_qkv, cudaFuncAttributeMaxDynamicSharedMemorySize, GEMM_SMEM);
    cudaFuncSetAttribute(gemm_fc1, cudaFuncAttributeMaxDynamicSharedMemorySize, GEMM_SMEM);

    bm_kernel<<<(8 * NH * NWIN * NWIN + 255) / 256, 256>>>(relt, mask);
    prepack_kernel<<<(5 * 9216 + 255) / 256, 256>>>(qkvw, projw, fc1w);
    gemm_qkv<<<MTOT / 128, 256, GEMM_SMEM>>>(x, n1w, n1b, qkvb);
    attn_proj_kernel<<<BTOT, 224, AP_SMEM>>>(projb);
    gemm_fc1<<<MTOT / 128, 256, GEMM_SMEM>>>(fc1b, x, out);
}

// round 8
// speedup vs baseline: 1.2438x; 1.2438x over previous
#include <cuda_runtime.h>
#include <cuda_fp16.h>
#include <math.h>
#include <stdint.h>

// ---- problem constants ----
#define NWIN 98
#define NH 3
#define HD 32
#define CD 96
#define DD 16
#define HH 112
#define WW2 112
#define NWX 2048
#define BATCH 2
#define BTOT (BATCH*NWX)      // 4096
#define MTOT (BTOT*NWIN)      // 401408
#define LTOT (DD*HH*WW2)      // 200704
#define SCALE 0.17677669529663689f

// ---- scratch (fp16 intermediates: half the HBM traffic) ----
__device__ __half g_q[(size_t)BTOT*NH*NWIN*HD];   // (b_,h,n,hd), q pre-scaled
__device__ __half g_k[(size_t)BTOT*NH*NWIN*HD];
__device__ __half g_v[(size_t)BTOT*NH*NWIN*HD];
__device__ __half g_ao[(size_t)MTOT*CD];
__device__ __half g_y[(size_t)MTOT*CD];           // scattered spatial
__device__ float g_bm[8*NH*NWIN*NWIN];            // bias+mask per (class, head)
__device__ unsigned g_Bp[5*9216];                 // prepacked B frags (tf32 bits)

// ---- helpers ----
__device__ __forceinline__ unsigned f2tf(float x) {
    unsigned r;
    asm("cvt.rna.tf32.f32 %0, %1;" : "=r"(r) : "f"(x));
    return r;
}
// 2 packed halves -> 2 fp32 bit patterns (exact; valid tf32 operands)
__device__ __forceinline__ uint2 h2u(unsigned h) {
    __half2 hh = *(__half2*)&h;
    float2 f = __half22float2(hh);
    return make_uint2(__float_as_uint(f.x), __float_as_uint(f.y));
}
__device__ __forceinline__ void mma_tf32(float* d, uint4 a, uint2 b) {
    asm volatile(
        "mma.sync.aligned.m16n8k8.row.col.f32.tf32.tf32.f32 "
        "{%0,%1,%2,%3}, {%4,%5,%6,%7}, {%8,%9}, {%0,%1,%2,%3};"
        : "+f"(d[0]), "+f"(d[1]), "+f"(d[2]), "+f"(d[3])
        : "r"(a.x), "r"(a.y), "r"(a.z), "r"(a.w), "r"(b.x), "r"(b.y));
}

// ============ K0a: combined bias+mask table ============
__global__ void bm_kernel(const float* __restrict__ table,
                          const float* __restrict__ mask) {
    int idx = blockIdx.x * blockDim.x + threadIdx.x;
    if (idx >= 8 * NH * NWIN * NWIN) return;
    int cls = idx / (NH * NWIN * NWIN);
    int rem = idx % (NH * NWIN * NWIN);
    int head = rem / (NWIN * NWIN);
    int r = rem % (NWIN * NWIN);
    int n = r / NWIN, m = r % NWIN;
    int d1 = n / 49, h1 = (n % 49) / 7, w1 = n % 7;
    int d2 = m / 49, h2 = (m % 49) / 7, w2 = m % 7;
    int t = (d1 - d2 + 1) * 169 + (h1 - h2 + 6) * 13 + (w1 - w2 + 6);
    int wd = (cls & 4) ? 7 : 0;
    int wh = (cls & 2) ? 15 : 0;
    int ww = (cls & 1) ? 15 : 0;
    int widx = wd * 256 + wh * 16 + ww;
    g_bm[idx] = table[t * NH + head] + mask[(size_t)widx * (NWIN * NWIN) + r];
}

// ============ K0b: prepack weights into MMA B-fragment layout ============
__global__ void prepack_kernel(const float* __restrict__ qkvw,
                               const float* __restrict__ projw,
                               const float* __restrict__ fc1w) {
    int idx = blockIdx.x * blockDim.x + threadIdx.x;
    if (idx >= 5 * 9216) return;
    int mat = idx / 9216, rem = idx % 9216;
    int c = rem / 96, k = rem % 96;
    float v;
    if (mat < 3) v = qkvw[(size_t)(mat * 96 + c) * 96 + k];
    else if (mat == 3) v = projw[(size_t)c * 96 + k];
    else v = fc1w[(size_t)c * 96 + k];
    int word = (((c >> 3) * 12 + (k >> 3)) * 32 + (c & 7) * 4 + (k & 3)) * 2 + ((k >> 2) & 1);
    g_Bp[mat * 9216 + word] = f2tf(v);
}

// ============ GEMM common ============
#define GEMM_SMEM ((12800 + 9216) * 4)

__device__ __forceinline__ void mma12(float d[12][4], const unsigned* sAu,
                                      const unsigned* sB, int r0, int tig, int lane) {
    const uint2* b2 = (const uint2*)sB;
    #pragma unroll
    for (int kt = 0; kt < 12; kt++) {
        uint4 af;
        af.x = sAu[r0 * 100 + kt * 8 + tig];
        af.y = sAu[(r0 + 8) * 100 + kt * 8 + tig];
        af.z = sAu[r0 * 100 + kt * 8 + tig + 4];
        af.w = sAu[(r0 + 8) * 100 + kt * 8 + tig + 4];
        #pragma unroll
        for (int nt = 0; nt < 12; nt++) {
            uint2 bf = b2[(nt * 12 + kt) * 32 + lane];
            mma_tf32(d[nt], af, bf);
        }
    }
}

// ============ K1: fused LayerNorm + window-partition + QKV GEMM ============
__global__ __launch_bounds__(256, 2)
void gemm_qkv(const float* __restrict__ x,
              const float* __restrict__ nw,
              const float* __restrict__ nb,
              const float* __restrict__ bias) {
    extern __shared__ unsigned smu[];
    unsigned* sAu = smu;          // [128][100] tf32 bits
    unsigned* sB  = smu + 12800;
    int rowbase = blockIdx.x * 128;
    int tid = threadIdx.x;
    int w = tid >> 5, lane = tid & 31;
    int g = lane >> 2, tig = lane & 3;

    float nw0 = nw[lane], nw1 = nw[lane + 32], nw2 = nw[lane + 64];
    float nb0 = nb[lane], nb1 = nb[lane + 32], nb2 = nb[lane + 64];

    // ---- phase A: gather (shift+window) + LayerNorm -> sAu ----
    for (int i = 0; i < 16; i++) {
        int r = w * 16 + i;
        int m = rowbase + r;
        int b_ = m / NWIN, n = m % NWIN;
        int b = b_ >> 11;
        int widx = b_ & (NWX - 1);
        int wd = widx >> 8, wh = (widx >> 4) & 15, ww = widx & 15;
        int nd = n / 49, nr = n % 49, nh2 = nr / 7, nw2i = nr % 7;
        int dp = wd * 2 + nd, hp = wh * 7 + nh2, wp = ww * 7 + nw2i;
        int d = dp + 1; if (d >= DD) d -= DD;
        int h = hp + 3; if (h >= HH) h -= HH;
        int wq = wp + 3; if (wq >= WW2) wq -= WW2;
        size_t src = ((size_t)b * LTOT + (size_t)(d * (HH * WW2) + h * WW2 + wq)) * CD;
        float v0 = x[src + lane], v1 = x[src + 32 + lane], v2 = x[src + 64 + lane];
        float s = v0 + v1 + v2;
        float ss = v0 * v0 + v1 * v1 + v2 * v2;
        #pragma unroll
        for (int o = 16; o; o >>= 1) {
            s  += __shfl_xor_sync(0xffffffffu, s, o);
            ss += __shfl_xor_sync(0xffffffffu, ss, o);
        }
        float mean = s * (1.0f / 96.0f);
        float var = ss * (1.0f / 96.0f) - mean * mean;
        float rs = rsqrtf(var + 1e-5f);
        sAu[r * 100 + lane]      = f2tf((v0 - mean) * rs * nw0 + nb0);
        sAu[r * 100 + lane + 32] = f2tf((v1 - mean) * rs * nw1 + nb1);
        sAu[r * 100 + lane + 64] = f2tf((v2 - mean) * rs * nw2 + nb2);
    }

    int m0 = rowbase + w * 16 + g;
    int b0 = m0 / NWIN, n0 = m0 % NWIN;
    int b1 = (m0 + 8) / NWIN, n1 = (m0 + 8) % NWIN;
    int r0 = w * 16 + g;
    __syncthreads();

    // ---- phase B: loop q/k/v weight parts ----
    for (int p = 0; p < 3; p++) {
        if (p > 0) __syncthreads();
        {
            const uint4* s4 = (const uint4*)(g_Bp + p * 9216);
            uint4* d4 = (uint4*)sB;
            #pragma unroll
            for (int i = 0; i < 9; i++) d4[tid + i * 256] = s4[tid + i * 256];
        }
        __syncthreads();
        float d[12][4];
        #pragma unroll
        for (int nt = 0; nt < 12; nt++)
            #pragma unroll
            for (int r = 0; r < 4; r++) d[nt][r] = 0.0f;
        mma12(d, sAu, sB, r0, tig, lane);

        __half* dstbuf = (p == 0) ? g_q : (p == 1) ? g_k : g_v;
        float sc = (p == 0) ? SCALE : 1.0f;
        #pragma unroll
        for (int nt = 0; nt < 12; nt++) {
            int c = nt * 8 + tig * 2;
            int head = c >> 5, wd = c & 31;
            float bx = bias[p * 96 + c], by = bias[p * 96 + c + 1];
            *(__half2*)(dstbuf + ((((size_t)b0 * NH + head) * NWIN + n0) * HD + wd)) =
                __floats2half2_rn((d[nt][0] + bx) * sc, (d[nt][1] + by) * sc);
            *(__half2*)(dstbuf + ((((size_t)b1 * NH + head) * NWIN + n1) * HD + wd)) =
                __floats2half2_rn((d[nt][2] + bx) * sc, (d[nt][3] + by) * sc);
        }
    }
}

// ============ proj / fc1 GEMM (A operand: fp16 in global) ============
template<int EPI>
__global__ __launch_bounds__(256, 2)
void gemm_tc(const float* __restrict__ bias,
             const float* __restrict__ resid,
             float* __restrict__ out) {
    extern __shared__ unsigned smu[];
    unsigned* sAu = smu;
    unsigned* sB  = smu + 12800;
    const __half* A = (EPI == 1) ? g_ao : g_y;
    int rowbase = blockIdx.x * 128;
    int tid = threadIdx.x;
    int w = tid >> 5, lane = tid & 31;
    int g = lane >> 2, tig = lane & 3;
    int r0 = w * 16 + g;

    // ---- stage A: uint4 (8 halves) -> 8 fp32 bits ----
    {
        const uint4* A4 = (const uint4*)(A + (size_t)rowbase * 96);
        #pragma unroll
        for (int it = 0; it < 6; it++) {
            int idx = tid + it * 256;   // 1536 = 128 rows x 12
            int r = idx / 12, k8 = idx % 12;
            uint4 v = A4[idx];
            uint2 a0 = h2u(v.x), a1 = h2u(v.y), a2 = h2u(v.z), a3 = h2u(v.w);
            *(uint4*)(sAu + r * 100 + k8 * 8)     = make_uint4(a0.x, a0.y, a1.x, a1.y);
            *(uint4*)(sAu + r * 100 + k8 * 8 + 4) = make_uint4(a2.x, a2.y, a3.x, a3.y);
        }
    }
    // ---- stage B: copy prepacked frags ----
    {
        const uint4* s4 = (const uint4*)(g_Bp + (EPI == 1 ? 3 : 4) * 9216);
        uint4* d4 = (uint4*)sB;
        #pragma unroll
        for (int i = 0; i < 9; i++) d4[tid + i * 256] = s4[tid + i * 256];
    }
    __syncthreads();

    float d[12][4];
    #pragma unroll
    for (int nt = 0; nt < 12; nt++)
        #pragma unroll
        for (int r = 0; r < 4; r++) d[nt][r] = 0.0f;
    mma12(d, sAu, sB, r0, tig, lane);

    if (EPI == 1) {
        size_t rowdst[2];
        #pragma unroll
        for (int rr = 0; rr < 2; rr++) {
            int m = rowbase + r0 + rr * 8;
            int b_ = m / NWIN, n = m % NWIN;
            int b = b_ >> 11;
            int widx = b_ & (NWX - 1);
            int wd = widx >> 8, wh = (widx >> 4) & 15, ww = widx & 15;
            int nd = n / 49, nr = n % 49, nh2 = nr / 7, nw2 = nr % 7;
            int dp = wd * 2 + nd, hp = wh * 7 + nh2, wp = ww * 7 + nw2;
            int dd = dp + 1; if (dd >= DD) dd -= DD;
            int hh = hp + 3; if (hh >= HH) hh -= HH;
            int ww3 = wp + 3; if (ww3 >= WW2) ww3 -= WW2;
            rowdst[rr] = ((size_t)b * LTOT +
                          (size_t)(dd * (HH * WW2) + hh * WW2 + ww3)) * CD;
        }
        #pragma unroll
        for (int nt = 0; nt < 12; nt++) {
            int c = nt * 8 + tig * 2;
            float bx = bias[c], by = bias[c + 1];
            *(__half2*)(g_y + rowdst[0] + c) = __floats2half2_rn(d[nt][0] + bx, d[nt][1] + by);
            *(__half2*)(g_y + rowdst[1] + c) = __floats2half2_rn(d[nt][2] + bx, d[nt][3] + by);
        }
    } else {
        int m0 = rowbase + r0;
        #pragma unroll
        for (int nt = 0; nt < 12; nt++) {
            int c = nt * 8 + tig * 2;
            float bx = bias[c], by = bias[c + 1];
            #pragma unroll
            for (int rr = 0; rr < 2; rr++) {
                size_t o = (size_t)(m0 + rr * 8) * CD + c;
                float v0 = d[nt][rr * 2] + bx;
                float v1 = d[nt][rr * 2 + 1] + by;
                float g0 = 0.5f * v0 * (1.0f + erff(v0 * 0.70710678118654752f));
                float g1 = 0.5f * v1 * (1.0f + erff(v1 * 0.70710678118654752f));
                float2 rv = *(const float2*)(resid + o);
                *(float2*)(out + o) = make_float2(rv.x + g0, rv.y + g1);
            }
        }
    }
}

// ============ K3: tensor-core window attention (fp16 in, tf32 MMA) ============
// smem (u32 words):
//   q_u [112][36] = 4032  @ 0
//   k_u [104][36] = 3744  @ 4032
//   Ss  [98][108] = 10584 @ 0   (float, overlays q_u/k_u after S phase)
//   vT  [32][108] = 3456  @ 10584
// total = 14040 words = 56160 B -> 4 CTAs/SM
#define ATTN_SMEM (14040 * 4)
__global__ __launch_bounds__(224, 4)
void attn_kernel() {
    extern __shared__ unsigned smu[];
    unsigned* q_u = smu;
    unsigned* k_u = smu + 4032;
    float* Ss = (float*)smu;
    unsigned* vT = smu + 10584;

    int b_ = blockIdx.x;
    int head = blockIdx.y;
    int tid = threadIdx.x;
    int w = tid >> 5, lane = tid & 31;
    int g = lane >> 2, tig = lane & 3;
    size_t bh = (size_t)b_ * NH + head;

    // ---- load q/k (uint4 = 8 halves), unpack to fp32 bits ----
    {
        const uint4* q4 = (const uint4*)(g_q + bh * (NWIN * HD));
        const uint4* k4 = (const uint4*)(g_k + bh * (NWIN * HD));
        for (int i4 = tid; i4 < 392; i4 += 224) {
            int n = i4 >> 2, c = (i4 & 3) << 3;
            uint4 qv = q4[i4];
            uint4 kv = k4[i4];
            uint2 a0 = h2u(qv.x), a1 = h2u(qv.y), a2 = h2u(qv.z), a3 = h2u(qv.w);
            *(uint4*)(q_u + n * 36 + c)     = make_uint4(a0.x, a0.y, a1.x, a1.y);
            *(uint4*)(q_u + n * 36 + c + 4) = make_uint4(a2.x, a2.y, a3.x, a3.y);
            uint2 b0 = h2u(kv.x), b1 = h2u(kv.y), b2 = h2u(kv.z), b3 = h2u(kv.w);
            *(uint4*)(k_u + n * 36 + c)     = make_uint4(b0.x, b0.y, b1.x, b1.y);
            *(uint4*)(k_u + n * 36 + c + 4) = make_uint4(b2.x, b2.y, b3.x, b3.y);
        }
        // v: transpose into vT[dim][token]
        const uint4* v4 = (const uint4*)(g_v + bh * (NWIN * HD));
        for (int i4 = tid; i4 < 392; i4 += 224) {
            int c4 = i4 / 98, n = i4 - c4 * 98;
            uint4 vv = v4[n * 4 + c4];
            int c = c4 * 8;
            uint2 b0 = h2u(vv.x), b1 = h2u(vv.y), b2 = h2u(vv.z), b3 = h2u(vv.w);
            vT[(c + 0) * 108 + n] = b0.x;
            vT[(c + 1) * 108 + n] = b0.y;
            vT[(c + 2) * 108 + n] = b1.x;
            vT[(c + 3) * 108 + n] = b1.y;
            vT[(c + 4) * 108 + n] = b2.x;
            vT[(c + 5) * 108 + n] = b2.y;
            vT[(c + 6) * 108 + n] = b3.x;
            vT[(c + 7) * 108 + n] = b3.y;
        }
        // zero pad tokens 98..103 for all 32 dims
        for (int i = tid; i < 192; i += 224) {
            int dim = i / 6, t = 98 + (i % 6);
            vT[dim * 108 + t] = 0u;
        }
    }
    __syncthreads();

    int r0 = w * 16 + g;
    // ---- S = Q K^T ----
    float d[13][4];
    #pragma unroll
    for (int nt = 0; nt < 13; nt++)
        #pragma unroll
        for (int r = 0; r < 4; r++) d[nt][r] = 0.0f;
    {
        uint4 af[4];
        #pragma unroll
        for (int kt = 0; kt < 4; kt++) {
            af[kt].x = q_u[r0 * 36 + kt * 8 + tig];
            af[kt].y = q_u[(r0 + 8) * 36 + kt * 8 + tig];
            af[kt].z = q_u[r0 * 36 + kt * 8 + tig + 4];
            af[kt].w = q_u[(r0 + 8) * 36 + kt * 8 + tig + 4];
        }
        #pragma unroll
        for (int nt = 0; nt < 13; nt++) {
            #pragma unroll
            for (int kt = 0; kt < 4; kt++) {
                uint2 bf;
                bf.x = k_u[(nt * 8 + g) * 36 + kt * 8 + tig];
                bf.y = k_u[(nt * 8 + g) * 36 + kt * 8 + tig + 4];
                mma_tf32(d[nt], af[kt], bf);
            }
        }
    }
    __syncthreads();   // q/k reads done; region becomes Ss

    bool v0 = r0 < 98, v1 = (r0 + 8) < 98;
    // ---- bias/mask + exp + row-sum in registers ----
    {
        int widx = b_ & (NWX - 1);
        int cls = (((widx >> 8) == 7) << 2) | ((((widx >> 4) & 15) == 15) << 1) |
                  ((widx & 15) == 15);
        const float* bmp = g_bm + (size_t)(cls * NH + head) * (NWIN * NWIN);
        float s0 = 0.0f, s1 = 0.0f;
        #pragma unroll
        for (int nt = 0; nt < 13; nt++) {
            int c0 = nt * 8 + tig * 2;
            float e0 = 0.f, e1 = 0.f, e2 = 0.f, e3 = 0.f;
            if (c0 < 98) {
                if (v0) {
                    float2 bb = __ldg((const float2*)(bmp + r0 * 98 + c0));
                    e0 = __expf(d[nt][0] + bb.x);
                    e1 = __expf(d[nt][1] + bb.y);
                }
                if (v1) {
                    float2 bb = __ldg((const float2*)(bmp + (r0 + 8) * 98 + c0));
                    e2 = __expf(d[nt][2] + bb.x);
                    e3 = __expf(d[nt][3] + bb.y);
                }
            }
            d[nt][0] = e0; d[nt][1] = e1; d[nt][2] = e2; d[nt][3] = e3;
            s0 += e0 + e1; s1 += e2 + e3;
        }
        s0 += __shfl_xor_sync(0xffffffffu, s0, 1);
        s0 += __shfl_xor_sync(0xffffffffu, s0, 2);
        s1 += __shfl_xor_sync(0xffffffffu, s1, 1);
        s1 += __shfl_xor_sync(0xffffffffu, s1, 2);
        float i0 = v0 ? (1.0f / s0) : 0.0f;
        float i1 = v1 ? (1.0f / s1) : 0.0f;
        #pragma unroll
        for (int nt = 0; nt < 13; nt++) {
            int c0 = nt * 8 + tig * 2;
            if (v0) *(float2*)(Ss + r0 * 108 + c0) =
                make_float2(d[nt][0] * i0, d[nt][1] * i0);
            if (v1) *(float2*)(Ss + (r0 + 8) * 108 + c0) =
                make_float2(d[nt][2] * i1, d[nt][3] * i1);
        }
    }
    __syncthreads();

    // ---- O = P V ----
    {
        int rA = v0 ? r0 : 0;
        int rB = v1 ? (r0 + 8) : 0;
        unsigned mA = v0 ? 0xffffffffu : 0u;
        unsigned mB = v1 ? 0xffffffffu : 0u;
        float o[4][4];
        #pragma unroll
        for (int nt = 0; nt < 4; nt++)
            #pragma unroll
            for (int r = 0; r < 4; r++) o[nt][r] = 0.0f;
        #pragma unroll
        for (int kt = 0; kt < 13; kt++) {
            uint4 af;
            af.x = f2tf(Ss[rA * 108 + kt * 8 + tig]) & mA;
            af.y = f2tf(Ss[rB * 108 + kt * 8 + tig]) & mB;
            af.z = f2tf(Ss[rA * 108 + kt * 8 + tig + 4]) & mA;
            af.w = f2tf(Ss[rB * 108 + kt * 8 + tig + 4]) & mB;
            #pragma unroll
            for (int nt = 0; nt < 4; nt++) {
                uint2 bf;
                bf.x = vT[(nt * 8 + g) * 108 + kt * 8 + tig];
                bf.y = vT[(nt * 8 + g) * 108 + kt * 8 + tig + 4];
                mma_tf32(o[nt], af, bf);
            }
        }
        #pragma unroll
        for (int nt = 0; nt < 4; nt++) {
            int c = nt * 8 + tig * 2;
            if (v0)
                *(__half2*)(g_ao + ((size_t)b_ * NWIN + r0) * CD + head * HD + c) =
                    __floats2half2_rn(o[nt][0], o[nt][1]);
            if (v1)
                *(__half2*)(g_ao + ((size_t)b_ * NWIN + r0 + 8) * CD + head * HD + c) =
                    __floats2half2_rn(o[nt][2], o[nt][3]);
        }
    }
}

// ============ launch ============
extern "C" void kernel_launch(void* const* d_in, const int* in_sizes, int n_in,
                              void* d_out, int out_size) {
    const float* x     = (const float*)d_in[0];
    const float* mask  = (const float*)d_in[1];
    const float* n1w   = (const float*)d_in[2];
    const float* n1b   = (const float*)d_in[3];
    const float* qkvw  = (const float*)d_in[4];
    const float* qkvb  = (const float*)d_in[5];
    const float* relt  = (const float*)d_in[6];
    const float* projw = (const float*)d_in[7];
    const float* projb = (const float*)d_in[8];
    const float* fc1w  = (const float*)d_in[9];
    const float* fc1b  = (const float*)d_in[10];
    float* out = (float*)d_out;

    cudaFuncSetAttribute(attn_kernel, cudaFuncAttributeMaxDynamicSharedMemorySize, ATTN_SMEM);
    cudaFuncSetAttribute(gemm_qkv, cudaFuncAttributeMaxDynamicSharedMemorySize, GEMM_SMEM);
    cudaFuncSetAttribute(gemm_tc<1>, cudaFuncAttributeMaxDynamicSharedMemorySize, GEMM_SMEM);
    cudaFuncSetAttribute(gemm_tc<2>, cudaFuncAttributeMaxDynamicSharedMemorySize, GEMM_SMEM);

    bm_kernel<<<(8 * NH * NWIN * NWIN + 255) / 256, 256>>>(relt, mask);
    prepack_kernel<<<(5 * 9216 + 255) / 256, 256>>>(qkvw, projw, fc1w);
    gemm_qkv<<<MTOT / 128, 256, GEMM_SMEM>>>(x, n1w, n1b, qkvb);
    attn_kernel<<<dim3(BTOT, NH), 224, ATTN_SMEM>>>();
    gemm_tc<1><<<MTOT / 128, 256, GEMM_SMEM>>>(projb, nullptr, nullptr);
    gemm_tc<2><<<MTOT / 128, 256, GEMM_SMEM>>>(fc1b, x, out);
}

// round 10
// speedup vs baseline: 1.5575x; 1.2522x over previous
#include <cuda_runtime.h>
#include <cuda_fp16.h>
#include <math.h>
#include <stdint.h>

// ---- problem constants ----
#define NWIN 98
#define NH 3
#define HD 32
#define CD 96
#define DD 16
#define HH 112
#define WW2 112
#define NWX 2048
#define BATCH 2
#define BTOT (BATCH*NWX)      // 4096
#define MTOT (BTOT*NWIN)      // 401408
#define LTOT (DD*HH*WW2)      // 200704
#define SCALE 0.17677669529663689f

// ---- scratch (fp16 intermediates) ----
__device__ __half g_q[(size_t)BTOT*NH*NWIN*HD];
__device__ __half g_k[(size_t)BTOT*NH*NWIN*HD];
__device__ __half g_v[(size_t)BTOT*NH*NWIN*HD];
__device__ __half g_ao[(size_t)MTOT*CD];
__device__ __half g_y[(size_t)MTOT*CD];
__device__ float g_bm[8*NH*NWIN*NWIN];
__device__ __half g_Bp[5*9216];     // prepacked fp16 B frags (m16n8k16)

// ---- helpers ----
__device__ __forceinline__ unsigned pack_h2(float a, float b) {
    __half2 h = __floats2half2_rn(a, b);
    return *(unsigned*)&h;
}
__device__ __forceinline__ void mma_f16(float* d, unsigned a0, unsigned a1,
                                        unsigned a2, unsigned a3,
                                        unsigned b0, unsigned b1) {
    asm volatile(
        "mma.sync.aligned.m16n8k16.row.col.f32.f16.f16.f32 "
        "{%0,%1,%2,%3}, {%4,%5,%6,%7}, {%8,%9}, {%0,%1,%2,%3};"
        : "+f"(d[0]), "+f"(d[1]), "+f"(d[2]), "+f"(d[3])
        : "r"(a0), "r"(a1), "r"(a2), "r"(a3), "r"(b0), "r"(b1));
}
__device__ __forceinline__ void ldsm_x4_trans(unsigned& r0, unsigned& r1,
                                              unsigned& r2, unsigned& r3,
                                              unsigned addr) {
    asm volatile("ldmatrix.sync.aligned.m8n8.x4.trans.shared.b16 {%0,%1,%2,%3}, [%4];"
        : "=r"(r0), "=r"(r1), "=r"(r2), "=r"(r3) : "r"(addr));
}

// ============ K0a: combined bias+mask table ============
__global__ void bm_kernel(const float* __restrict__ table,
                          const float* __restrict__ mask) {
    int idx = blockIdx.x * blockDim.x + threadIdx.x;
    if (idx >= 8 * NH * NWIN * NWIN) return;
    int cls = idx / (NH * NWIN * NWIN);
    int rem = idx % (NH * NWIN * NWIN);
    int head = rem / (NWIN * NWIN);
    int r = rem % (NWIN * NWIN);
    int n = r / NWIN, m = r % NWIN;
    int d1 = n / 49, h1 = (n % 49) / 7, w1 = n % 7;
    int d2 = m / 49, h2 = (m % 49) / 7, w2 = m % 7;
    int t = (d1 - d2 + 1) * 169 + (h1 - h2 + 6) * 13 + (w1 - w2 + 6);
    int wd = (cls & 4) ? 7 : 0;
    int wh = (cls & 2) ? 15 : 0;
    int ww = (cls & 1) ? 15 : 0;
    int widx = wd * 256 + wh * 16 + ww;
    g_bm[idx] = table[t * NH + head] + mask[(size_t)widx * (NWIN * NWIN) + r];
}

// ============ K0b: prepack weights into fp16 m16n8k16 B-fragment layout ============
__global__ void prepack_kernel(const float* __restrict__ qkvw,
                               const float* __restrict__ projw,
                               const float* __restrict__ fc1w) {
    int idx = blockIdx.x * blockDim.x + threadIdx.x;
    if (idx >= 5 * 9216) return;
    int mat = idx / 9216, rem = idx % 9216;
    int c = rem / 96, k = rem % 96;
    float v;
    if (mat < 3) v = qkvw[(size_t)(mat * 96 + c) * 96 + k];
    else if (mat == 3) v = projw[(size_t)c * 96 + k];
    else v = fc1w[(size_t)c * 96 + k];
    int nt = c >> 3, g = c & 7, kt = k >> 4, w16 = k & 15;
    int reg = w16 >> 3, tig = (w16 & 7) >> 1, lo = w16 & 1;
    int hidx = ((((nt * 6 + kt) * 32) + g * 4 + tig) * 2 + reg) * 2 + lo;
    g_Bp[mat * 9216 + hidx] = __float2half_rn(v);
}

// ============ GEMM common ============
// sAh: [128 rows][104 halves] = 6656 words; sB: 4608 words
#define GEMM_SMEM ((6656 + 4608) * 4)

__device__ __forceinline__ void mma6(float d[12][4], const unsigned* sAw,
                                     const unsigned* sB, int r0, int tig, int lane) {
    const uint2* b2 = (const uint2*)sB;
    #pragma unroll
    for (int kt = 0; kt < 6; kt++) {
        unsigned a0 = sAw[r0 * 52 + kt * 8 + tig];
        unsigned a1 = sAw[(r0 + 8) * 52 + kt * 8 + tig];
        unsigned a2 = sAw[r0 * 52 + kt * 8 + tig + 4];
        unsigned a3 = sAw[(r0 + 8) * 52 + kt * 8 + tig + 4];
        #pragma unroll
        for (int nt = 0; nt < 12; nt++) {
            uint2 bf = b2[(nt * 6 + kt) * 32 + lane];
            mma_f16(d[nt], a0, a1, a2, a3, bf.x, bf.y);
        }
    }
}

// ============ K1: fused LayerNorm + window-partition + QKV GEMM ============
__global__ __launch_bounds__(256, 2)
void gemm_qkv(const float* __restrict__ x,
              const float* __restrict__ nw,
              const float* __restrict__ nb,
              const float* __restrict__ bias) {
    extern __shared__ unsigned smu[];
    unsigned* sAw = smu;            // [128][52] words (fp16 pairs)
    __half* sAh = (__half*)smu;
    unsigned* sB = smu + 6656;
    int rowbase = blockIdx.x * 128;
    int tid = threadIdx.x;
    int w = tid >> 5, lane = tid & 31;
    int g = lane >> 2, tig = lane & 3;

    float nw0 = nw[lane], nw1 = nw[lane + 32], nw2 = nw[lane + 64];
    float nb0 = nb[lane], nb1 = nb[lane + 32], nb2 = nb[lane + 64];

    // ---- phase A: gather (shift+window) + LayerNorm -> fp16 smem ----
    for (int i = 0; i < 16; i++) {
        int r = w * 16 + i;
        int m = rowbase + r;
        int b_ = m / NWIN, n = m % NWIN;
        int b = b_ >> 11;
        int widx = b_ & (NWX - 1);
        int wd = widx >> 8, wh = (widx >> 4) & 15, ww = widx & 15;
        int nd = n / 49, nr = n % 49, nh2 = nr / 7, nw2i = nr % 7;
        int dp = wd * 2 + nd, hp = wh * 7 + nh2, wp = ww * 7 + nw2i;
        int d = dp + 1; if (d >= DD) d -= DD;
        int h = hp + 3; if (h >= HH) h -= HH;
        int wq = wp + 3; if (wq >= WW2) wq -= WW2;
        size_t src = ((size_t)b * LTOT + (size_t)(d * (HH * WW2) + h * WW2 + wq)) * CD;
        float v0 = x[src + lane], v1 = x[src + 32 + lane], v2 = x[src + 64 + lane];
        float s = v0 + v1 + v2;
        float ss = v0 * v0 + v1 * v1 + v2 * v2;
        #pragma unroll
        for (int o = 16; o; o >>= 1) {
            s  += __shfl_xor_sync(0xffffffffu, s, o);
            ss += __shfl_xor_sync(0xffffffffu, ss, o);
        }
        float mean = s * (1.0f / 96.0f);
        float var = ss * (1.0f / 96.0f) - mean * mean;
        float rs = rsqrtf(var + 1e-5f);
        sAh[r * 104 + lane]      = __float2half_rn((v0 - mean) * rs * nw0 + nb0);
        sAh[r * 104 + lane + 32] = __float2half_rn((v1 - mean) * rs * nw1 + nb1);
        sAh[r * 104 + lane + 64] = __float2half_rn((v2 - mean) * rs * nw2 + nb2);
    }

    int m0 = rowbase + w * 16 + g;
    int b0 = m0 / NWIN, n0 = m0 % NWIN;
    int b1 = (m0 + 8) / NWIN, n1 = (m0 + 8) % NWIN;
    int r0 = w * 16 + g;
    __syncthreads();

    for (int p = 0; p < 3; p++) {
        if (p > 0) __syncthreads();
        {
            const uint4* s4 = (const uint4*)(g_Bp + (size_t)p * 9216);
            uint4* d4 = (uint4*)sB;
            for (int i = tid; i < 1152; i += 256) d4[i] = s4[i];
        }
        __syncthreads();
        float d[12][4];
        #pragma unroll
        for (int nt = 0; nt < 12; nt++)
            #pragma unroll
            for (int r = 0; r < 4; r++) d[nt][r] = 0.0f;
        mma6(d, sAw, sB, r0, tig, lane);

        __half* dstbuf = (p == 0) ? g_q : (p == 1) ? g_k : g_v;
        float sc = (p == 0) ? SCALE : 1.0f;
        #pragma unroll
        for (int nt = 0; nt < 12; nt++) {
            int c = nt * 8 + tig * 2;
            int head = c >> 5, wd = c & 31;
            float bx = bias[p * 96 + c], by = bias[p * 96 + c + 1];
            *(unsigned*)(dstbuf + ((((size_t)b0 * NH + head) * NWIN + n0) * HD + wd)) =
                pack_h2((d[nt][0] + bx) * sc, (d[nt][1] + by) * sc);
            *(unsigned*)(dstbuf + ((((size_t)b1 * NH + head) * NWIN + n1) * HD + wd)) =
                pack_h2((d[nt][2] + bx) * sc, (d[nt][3] + by) * sc);
        }
    }
}

// ============ proj / fc1 GEMM (A: fp16 global, pure copy staging) ============
template<int EPI>
__global__ __launch_bounds__(256, 2)
void gemm_tc(const float* __restrict__ bias,
             const float* __restrict__ resid,
             float* __restrict__ out) {
    extern __shared__ unsigned smu[];
    unsigned* sAw = smu;
    unsigned* sB = smu + 6656;
    const __half* A = (EPI == 1) ? g_ao : g_y;
    int rowbase = blockIdx.x * 128;
    int tid = threadIdx.x;
    int w = tid >> 5, lane = tid & 31;
    int g = lane >> 2, tig = lane & 3;
    int r0 = w * 16 + g;

    {
        const uint4* A4 = (const uint4*)(A + (size_t)rowbase * 96);
        #pragma unroll
        for (int it = 0; it < 6; it++) {
            int idx = tid + it * 256;   // 1536
            int r = idx / 12, k8 = idx % 12;
            *(uint4*)(sAw + r * 52 + k8 * 4) = A4[idx];
        }
    }
    {
        const uint4* s4 = (const uint4*)(g_Bp + (size_t)(EPI == 1 ? 3 : 4) * 9216);
        uint4* d4 = (uint4*)sB;
        for (int i = tid; i < 1152; i += 256) d4[i] = s4[i];
    }
    __syncthreads();

    float d[12][4];
    #pragma unroll
    for (int nt = 0; nt < 12; nt++)
        #pragma unroll
        for (int r = 0; r < 4; r++) d[nt][r] = 0.0f;
    mma6(d, sAw, sB, r0, tig, lane);

    if (EPI == 1) {
        size_t rowdst[2];
        #pragma unroll
        for (int rr = 0; rr < 2; rr++) {
            int m = rowbase + r0 + rr * 8;
            int b_ = m / NWIN, n = m % NWIN;
            int b = b_ >> 11;
            int widx = b_ & (NWX - 1);
            int wd = widx >> 8, wh = (widx >> 4) & 15, ww = widx & 15;
            int nd = n / 49, nr = n % 49, nh2 = nr / 7, nw2 = nr % 7;
            int dp = wd * 2 + nd, hp = wh * 7 + nh2, wp = ww * 7 + nw2;
            int dd = dp + 1; if (dd >= DD) dd -= DD;
            int hh = hp + 3; if (hh >= HH) hh -= HH;
            int ww3 = wp + 3; if (ww3 >= WW2) ww3 -= WW2;
            rowdst[rr] = ((size_t)b * LTOT +
                          (size_t)(dd * (HH * WW2) + hh * WW2 + ww3)) * CD;
        }
        #pragma unroll
        for (int nt = 0; nt < 12; nt++) {
            int c = nt * 8 + tig * 2;
            float bx = bias[c], by = bias[c + 1];
            *(unsigned*)(g_y + rowdst[0] + c) = pack_h2(d[nt][0] + bx, d[nt][1] + by);
            *(unsigned*)(g_y + rowdst[1] + c) = pack_h2(d[nt][2] + bx, d[nt][3] + by);
        }
    } else {
        int m0 = rowbase + r0;
        #pragma unroll
        for (int nt = 0; nt < 12; nt++) {
            int c = nt * 8 + tig * 2;
            float bx = bias[c], by = bias[c + 1];
            #pragma unroll
            for (int rr = 0; rr < 2; rr++) {
                size_t o = (size_t)(m0 + rr * 8) * CD + c;
                float v0 = d[nt][rr * 2] + bx;
                float v1 = d[nt][rr * 2 + 1] + by;
                float g0 = 0.5f * v0 * (1.0f + erff(v0 * 0.70710678118654752f));
                float g1 = 0.5f * v1 * (1.0f + erff(v1 * 0.70710678118654752f));
                float2 rv = *(const float2*)(resid + o);
                *(float2*)(out + o) = make_float2(rv.x + g0, rv.y + g1);
            }
        }
    }
}

// ============ K3: fp16-MMA window attention ============
// smem (u32 words):
//   q_h [112][20w] = 2240 @ 0        (fp16 pairs; rows 98-111 garbage, unused outputs)
//   k_h [104][20w] = 2080 @ 2240
//   Ssh [98][60w]  = 5880 @ 0        (fp16 P, overlays q/k after S phase)
//   vs  [112][20w] = 2240 @ 5880     ([token][dim] fp16, rows 98-111 zeroed)
// total 8120 words = 32480 B -> 4 CTAs/SM
#define ATTN_SMEM (8120 * 4)
__global__ __launch_bounds__(224, 4)
void attn_kernel() {
    extern __shared__ unsigned smu[];
    unsigned* q_h = smu;
    unsigned* k_h = smu + 2240;
    unsigned* Ssh = smu;
    unsigned* vs = smu + 5880;

    int b_ = blockIdx.x;
    int head = blockIdx.y;
    int tid = threadIdx.x;
    int w = tid >> 5, lane = tid & 31;
    int g = lane >> 2, tig = lane & 3;
    size_t bh = (size_t)b_ * NH + head;

    // ---- load q/k/v: pure uint4 copies ----
    {
        const uint4* q4 = (const uint4*)(g_q + bh * (NWIN * HD));
        const uint4* k4 = (const uint4*)(g_k + bh * (NWIN * HD));
        const uint4* v4 = (const uint4*)(g_v + bh * (NWIN * HD));
        for (int i4 = tid; i4 < 392; i4 += 224) {
            int n = i4 >> 2, c4 = (i4 & 3) << 2;
            *(uint4*)(q_h + n * 20 + c4) = q4[i4];
            *(uint4*)(k_h + n * 20 + c4) = k4[i4];
            *(uint4*)(vs + n * 20 + c4) = v4[i4];
        }
        // zero vs pad rows 98..111 (avoid 0*garbage NaN in PV)
        for (int i = tid; i < 224; i += 224) {
            int n = 98 + (i >> 4), ww2 = i & 15;
            *(vs + n * 20 + ww2) = 0u;
        }
    }
    __syncthreads();

    int r0 = w * 16 + g;
    // ---- S = Q K^T : 13 nt x 2 kt fp16 MMAs ----
    float d[13][4];
    #pragma unroll
    for (int nt = 0; nt < 13; nt++)
        #pragma unroll
        for (int r = 0; r < 4; r++) d[nt][r] = 0.0f;
    {
        unsigned a[2][4];
        #pragma unroll
        for (int kt = 0; kt < 2; kt++) {
            a[kt][0] = q_h[r0 * 20 + kt * 8 + tig];
            a[kt][1] = q_h[(r0 + 8) * 20 + kt * 8 + tig];
            a[kt][2] = q_h[r0 * 20 + kt * 8 + tig + 4];
            a[kt][3] = q_h[(r0 + 8) * 20 + kt * 8 + tig + 4];
        }
        #pragma unroll
        for (int nt = 0; nt < 13; nt++) {
            #pragma unroll
            for (int kt = 0; kt < 2; kt++) {
                unsigned b0 = k_h[(nt * 8 + g) * 20 + kt * 8 + tig];
                unsigned b1 = k_h[(nt * 8 + g) * 20 + kt * 8 + tig + 4];
                mma_f16(d[nt], a[kt][0], a[kt][1], a[kt][2], a[kt][3], b0, b1);
            }
        }
    }
    __syncthreads();   // q/k reads done; region becomes Ssh

    bool v0 = r0 < 98, v1 = (r0 + 8) < 98;
    // ---- bias/mask + exp + row-sum in registers; store P as fp16 ----
    {
        int widx = b_ & (NWX - 1);
        int cls = (((widx >> 8) == 7) << 2) | ((((widx >> 4) & 15) == 15) << 1) |
                  ((widx & 15) == 15);
        const float* bmp = g_bm + (size_t)(cls * NH + head) * (NWIN * NWIN);
        float s0 = 0.0f, s1 = 0.0f;
        #pragma unroll
        for (int nt = 0; nt < 13; nt++) {
            int c0 = nt * 8 + tig * 2;
            float e0 = 0.f, e1 = 0.f, e2 = 0.f, e3 = 0.f;
            if (c0 < 98) {
                if (v0) {
                    float2 bb = __ldg((const float2*)(bmp + r0 * 98 + c0));
                    e0 = __expf(d[nt][0] + bb.x);
                    e1 = __expf(d[nt][1] + bb.y);
                }
                if (v1) {
                    float2 bb = __ldg((const float2*)(bmp + (r0 + 8) * 98 + c0));
                    e2 = __expf(d[nt][2] + bb.x);
                    e3 = __expf(d[nt][3] + bb.y);
                }
            }
            d[nt][0] = e0; d[nt][1] = e1; d[nt][2] = e2; d[nt][3] = e3;
            s0 += e0 + e1; s1 += e2 + e3;
        }
        s0 += __shfl_xor_sync(0xffffffffu, s0, 1);
        s0 += __shfl_xor_sync(0xffffffffu, s0, 2);
        s1 += __shfl_xor_sync(0xffffffffu, s1, 1);
        s1 += __shfl_xor_sync(0xffffffffu, s1, 2);
        float i0 = v0 ? (1.0f / s0) : 0.0f;
        float i1 = v1 ? (1.0f / s1) : 0.0f;
        #pragma unroll
        for (int nt = 0; nt < 13; nt++) {
            if (v0) Ssh[r0 * 60 + nt * 4 + tig] =
                pack_h2(d[nt][0] * i0, d[nt][1] * i0);
            if (v1) Ssh[(r0 + 8) * 60 + nt * 4 + tig] =
                pack_h2(d[nt][2] * i1, d[nt][3] * i1);
        }
        // zero P pad words (k=104..111) for rows 0..97
        for (int i = tid; i < 392; i += 224)
            Ssh[(i >> 2) * 60 + 52 + (i & 3)] = 0u;
    }
    __syncthreads();

    // ---- O = P V : 7 kt x 4 nt, V B-frags via ldmatrix.trans ----
    {
        int rA = v0 ? r0 : 0;
        int rB = v1 ? (r0 + 8) : 0;
        unsigned mA = v0 ? 0xffffffffu : 0u;
        unsigned mB = v1 ? 0xffffffffu : 0u;
        unsigned vs_addr = (unsigned)__cvta_generic_to_shared(vs);
        int sub = lane & 7, hsel = (lane >> 3) & 1, nsel = lane >> 4;
        float o[4][4];
        #pragma unroll
        for (int nt = 0; nt < 4; nt++)
            #pragma unroll
            for (int r = 0; r < 4; r++) o[nt][r] = 0.0f;
        #pragma unroll
        for (int kt = 0; kt < 7; kt++) {
            unsigned a0 = Ssh[rA * 60 + kt * 8 + tig] & mA;
            unsigned a1 = Ssh[rB * 60 + kt * 8 + tig] & mB;
            unsigned a2 = Ssh[rA * 60 + kt * 8 + tig + 4] & mA;
            unsigned a3 = Ssh[rB * 60 + kt * 8 + tig + 4] & mB;
            #pragma unroll
            for (int ntp = 0; ntp < 2; ntp++) {
                unsigned addr = vs_addr +
                    ((unsigned)((16 * kt + 8 * hsel + sub) * 40 +
                                8 * (ntp * 2 + nsel)) << 1);
                unsigned b0, b1, b2, b3;
                ldsm_x4_trans(b0, b1, b2, b3, addr);
                mma_f16(o[ntp * 2], a0, a1, a2, a3, b0, b1);
                mma_f16(o[ntp * 2 + 1], a0, a1, a2, a3, b2, b3);
            }
        }
        #pragma unroll
        for (int nt = 0; nt < 4; nt++) {
            int c = nt * 8 + tig * 2;
            if (v0)
                *(unsigned*)(g_ao + ((size_t)b_ * NWIN + r0) * CD + head * HD + c) =
                    pack_h2(o[nt][0], o[nt][1]);
            if (v1)
                *(unsigned*)(g_ao + ((size_t)b_ * NWIN + r0 + 8) * CD + head * HD + c) =
                    pack_h2(o[nt][2], o[nt][3]);
        }
    }
}

// ============ launch ============
extern "C" void kernel_launch(void* const* d_in, const int* in_sizes, int n_in,
                              void* d_out, int out_size) {
    const float* x     = (const float*)d_in[0];
    const float* mask  = (const float*)d_in[1];
    const float* n1w   = (const float*)d_in[2];
    const float* n1b   = (const float*)d_in[3];
    const float* qkvw  = (const float*)d_in[4];
    const float* qkvb  = (const float*)d_in[5];
    const float* relt  = (const float*)d_in[6];
    const float* projw = (const float*)d_in[7];
    const float* projb = (const float*)d_in[8];
    const float* fc1w  = (const float*)d_in[9];
    const float* fc1b  = (const float*)d_in[10];
    float* out = (float*)d_out;

    cudaFuncSetAttribute(attn_kernel, cudaFuncAttributeMaxDynamicSharedMemorySize, ATTN_SMEM);
    cudaFuncSetAttribute(gemm_qkv, cudaFuncAttributeMaxDynamicSharedMemorySize, GEMM_SMEM);
    cudaFuncSetAttribute(gemm_tc<1>, cudaFuncAttributeMaxDynamicSharedMemorySize, GEMM_SMEM);
    cudaFuncSetAttribute(gemm_tc<2>, cudaFuncAttributeMaxDynamicSharedMemorySize, GEMM_SMEM);

    bm_kernel<<<(8 * NH * NWIN * NWIN + 255) / 256, 256>>>(relt, mask);
    prepack_kernel<<<(5 * 9216 + 255) / 256, 256>>>(qkvw, projw, fc1w);
    gemm_qkv<<<MTOT / 128, 256, GEMM_SMEM>>>(x, n1w, n1b, qkvb);
    attn_kernel<<<dim3(BTOT, NH), 224, ATTN_SMEM>>>();
    gemm_tc<1><<<MTOT / 128, 256, GEMM_SMEM>>>(projb, nullptr, nullptr);
    gemm_tc<2><<<MTOT / 128, 256, GEMM_SMEM>>>(fc1b, x, out);
}

// round 11
// speedup vs baseline: 1.8769x; 1.2051x over previous
#include <cuda_runtime.h>
#include <cuda_fp16.h>
#include <math.h>
#include <stdint.h>

// ---- problem constants ----
#define NWIN 98
#define NH 3
#define HD 32
#define CD 96
#define DD 16
#define HH 112
#define WW2 112
#define NWX 2048
#define BATCH 2
#define BTOT (BATCH*NWX)      // 4096
#define MTOT (BTOT*NWIN)      // 401408
#define LTOT (DD*HH*WW2)      // 200704
#define SCALE 0.17677669529663689f

// ---- scratch (fp16 intermediates) ----
__device__ __half g_q[(size_t)BTOT*NH*NWIN*HD];
__device__ __half g_k[(size_t)BTOT*NH*NWIN*HD];
__device__ __half g_v[(size_t)BTOT*NH*NWIN*HD];
__device__ __half g_ao[(size_t)MTOT*CD];
__device__ __half g_y[(size_t)MTOT*CD];          // windowed-linear order now
__device__ __half g_bm[8*NH*NWIN*NWIN];          // fp16 bias+mask
__device__ __half g_Bp[5*9216];                  // prepacked fp16 B frags

// ---- helpers ----
__device__ __forceinline__ unsigned pack_h2(float a, float b) {
    __half2 h = __floats2half2_rn(a, b);
    return *(unsigned*)&h;
}
__device__ __forceinline__ void mma_f16(float* d, unsigned a0, unsigned a1,
                                        unsigned a2, unsigned a3,
                                        unsigned b0, unsigned b1) {
    asm volatile(
        "mma.sync.aligned.m16n8k16.row.col.f32.f16.f16.f32 "
        "{%0,%1,%2,%3}, {%4,%5,%6,%7}, {%8,%9}, {%0,%1,%2,%3};"
        : "+f"(d[0]), "+f"(d[1]), "+f"(d[2]), "+f"(d[3])
        : "r"(a0), "r"(a1), "r"(a2), "r"(a3), "r"(b0), "r"(b1));
}
__device__ __forceinline__ void ldsm_x4_trans(unsigned& r0, unsigned& r1,
                                              unsigned& r2, unsigned& r3,
                                              unsigned addr) {
    asm volatile("ldmatrix.sync.aligned.m8n8.x4.trans.shared.b16 {%0,%1,%2,%3}, [%4];"
        : "=r"(r0), "=r"(r1), "=r"(r2), "=r"(r3) : "r"(addr));
}

// ============ K0a: combined bias+mask table (fp16) ============
__global__ void bm_kernel(const float* __restrict__ table,
                          const float* __restrict__ mask) {
    int idx = blockIdx.x * blockDim.x + threadIdx.x;
    if (idx >= 8 * NH * NWIN * NWIN) return;
    int cls = idx / (NH * NWIN * NWIN);
    int rem = idx % (NH * NWIN * NWIN);
    int head = rem / (NWIN * NWIN);
    int r = rem % (NWIN * NWIN);
    int n = r / NWIN, m = r % NWIN;
    int d1 = n / 49, h1 = (n % 49) / 7, w1 = n % 7;
    int d2 = m / 49, h2 = (m % 49) / 7, w2 = m % 7;
    int t = (d1 - d2 + 1) * 169 + (h1 - h2 + 6) * 13 + (w1 - w2 + 6);
    int wd = (cls & 4) ? 7 : 0;
    int wh = (cls & 2) ? 15 : 0;
    int ww = (cls & 1) ? 15 : 0;
    int widx = wd * 256 + wh * 16 + ww;
    g_bm[idx] = __float2half_rn(table[t * NH + head] +
                                mask[(size_t)widx * (NWIN * NWIN) + r]);
}

// ============ K0b: prepack weights into fp16 m16n8k16 B-fragment layout ============
__global__ void prepack_kernel(const float* __restrict__ qkvw,
                               const float* __restrict__ projw,
                               const float* __restrict__ fc1w) {
    int idx = blockIdx.x * blockDim.x + threadIdx.x;
    if (idx >= 5 * 9216) return;
    int mat = idx / 9216, rem = idx % 9216;
    int c = rem / 96, k = rem % 96;
    float v;
    if (mat < 3) v = qkvw[(size_t)(mat * 96 + c) * 96 + k];
    else if (mat == 3) v = projw[(size_t)c * 96 + k];
    else v = fc1w[(size_t)c * 96 + k];
    int nt = c >> 3, g = c & 7, kt = k >> 4, w16 = k & 15;
    int reg = w16 >> 3, tig = (w16 & 7) >> 1, lo = w16 & 1;
    int hidx = ((((nt * 6 + kt) * 32) + g * 4 + tig) * 2 + reg) * 2 + lo;
    g_Bp[mat * 9216 + hidx] = __float2half_rn(v);
}

// ============ GEMM common ============
// sAh [128][104 halves] = 6656 words; sB 4608 words; rowmap 128 words
#define GEMM_SMEM ((6656 + 4608 + 128) * 4)

__device__ __forceinline__ void mma6(float d[12][4], const unsigned* sAw,
                                     const unsigned* sB, int r0, int tig, int lane) {
    const uint2* b2 = (const uint2*)sB;
    #pragma unroll
    for (int kt = 0; kt < 6; kt++) {
        unsigned a0 = sAw[r0 * 52 + kt * 8 + tig];
        unsigned a1 = sAw[(r0 + 8) * 52 + kt * 8 + tig];
        unsigned a2 = sAw[r0 * 52 + kt * 8 + tig + 4];
        unsigned a3 = sAw[(r0 + 8) * 52 + kt * 8 + tig + 4];
        #pragma unroll
        for (int nt = 0; nt < 12; nt++) {
            uint2 bf = b2[(nt * 6 + kt) * 32 + lane];
            mma_f16(d[nt], a0, a1, a2, a3, bf.x, bf.y);
        }
    }
}

// ============ K1: fused LayerNorm + window-partition + QKV GEMM ============
__global__ __launch_bounds__(256, 3)
void gemm_qkv(const float* __restrict__ x,
              const float* __restrict__ nw,
              const float* __restrict__ nb,
              const float* __restrict__ bias) {
    extern __shared__ unsigned smu[];
    unsigned* sAw = smu;            // [128][52] words
    __half* sAh = (__half*)smu;
    unsigned* sB = smu + 6656;
    int rowbase = blockIdx.x * 128;
    int tid = threadIdx.x;
    int w = tid >> 5, lane = tid & 31;
    int g = lane >> 2, tig = lane & 3;

    float nw0 = nw[lane], nw1 = nw[lane + 32], nw2 = nw[lane + 64];
    float nb0 = nb[lane], nb1 = nb[lane + 32], nb2 = nb[lane + 64];

    // ---- phase A: gather (shift+window) + LayerNorm -> fp16 smem ----
    #pragma unroll 2
    for (int i = 0; i < 16; i++) {
        int r = w * 16 + i;
        int m = rowbase + r;
        int b_ = m / NWIN, n = m % NWIN;
        int b = b_ >> 11;
        int widx = b_ & (NWX - 1);
        int wd = widx >> 8, wh = (widx >> 4) & 15, ww = widx & 15;
        int nd = n / 49, nr = n % 49, nh2 = nr / 7, nw2i = nr % 7;
        int dp = wd * 2 + nd, hp = wh * 7 + nh2, wp = ww * 7 + nw2i;
        int d = dp + 1; if (d >= DD) d -= DD;
        int h = hp + 3; if (h >= HH) h -= HH;
        int wq = wp + 3; if (wq >= WW2) wq -= WW2;
        size_t src = ((size_t)b * LTOT + (size_t)(d * (HH * WW2) + h * WW2 + wq)) * CD;
        float v0 = x[src + lane], v1 = x[src + 32 + lane], v2 = x[src + 64 + lane];
        float s = v0 + v1 + v2;
        float ss = v0 * v0 + v1 * v1 + v2 * v2;
        #pragma unroll
        for (int o = 16; o; o >>= 1) {
            s  += __shfl_xor_sync(0xffffffffu, s, o);
            ss += __shfl_xor_sync(0xffffffffu, ss, o);
        }
        float mean = s * (1.0f / 96.0f);
        float var = ss * (1.0f / 96.0f) - mean * mean;
        float rs = rsqrtf(var + 1e-5f);
        sAh[r * 104 + lane]      = __float2half_rn((v0 - mean) * rs * nw0 + nb0);
        sAh[r * 104 + lane + 32] = __float2half_rn((v1 - mean) * rs * nw1 + nb1);
        sAh[r * 104 + lane + 64] = __float2half_rn((v2 - mean) * rs * nw2 + nb2);
    }

    int m0 = rowbase + w * 16 + g;
    int b0 = m0 / NWIN, n0 = m0 % NWIN;
    int b1 = (m0 + 8) / NWIN, n1 = (m0 + 8) % NWIN;
    int r0 = w * 16 + g;
    __syncthreads();

    for (int p = 0; p < 3; p++) {
        if (p > 0) __syncthreads();
        {
            const uint4* s4 = (const uint4*)(g_Bp + (size_t)p * 9216);
            uint4* d4 = (uint4*)sB;
            for (int i = tid; i < 1152; i += 256) d4[i] = s4[i];
        }
        __syncthreads();
        float d[12][4];
        #pragma unroll
        for (int nt = 0; nt < 12; nt++)
            #pragma unroll
            for (int r = 0; r < 4; r++) d[nt][r] = 0.0f;
        mma6(d, sAw, sB, r0, tig, lane);

        __half* dstbuf = (p == 0) ? g_q : (p == 1) ? g_k : g_v;
        float sc = (p == 0) ? SCALE : 1.0f;
        #pragma unroll
        for (int nt = 0; nt < 12; nt++) {
            int c = nt * 8 + tig * 2;
            int head = c >> 5, wd = c & 31;
            float bx = bias[p * 96 + c], by = bias[p * 96 + c + 1];
            *(unsigned*)(dstbuf + ((((size_t)b0 * NH + head) * NWIN + n0) * HD + wd)) =
                pack_h2((d[nt][0] + bx) * sc, (d[nt][1] + by) * sc);
            *(unsigned*)(dstbuf + ((((size_t)b1 * NH + head) * NWIN + n1) * HD + wd)) =
                pack_h2((d[nt][2] + bx) * sc, (d[nt][3] + by) * sc);
        }
    }
}

// ============ proj (EPI=1): linear store / fc1 (EPI=2): gather + GELU + resid ============
template<int EPI>
__global__ __launch_bounds__(256, 3)
void gemm_tc(const float* __restrict__ bias,
             const float* __restrict__ resid,
             float* __restrict__ out) {
    extern __shared__ unsigned smu[];
    unsigned* sAw = smu;
    unsigned* sB = smu + 6656;
    int* rowmap = (int*)(smu + 11264);
    int rowbase = blockIdx.x * 128;
    int tid = threadIdx.x;
    int w = tid >> 5, lane = tid & 31;
    int g = lane >> 2, tig = lane & 3;
    int r0 = w * 16 + g;

    if (EPI == 2) {
        // inverse shift/window map: spatial row -> windowed-linear row of g_y
        if (tid < 128) {
            int m = rowbase + tid;
            int b = m / LTOT;
            int l = m - b * LTOT;
            int d = l / (HH * WW2);
            int rem = l - d * (HH * WW2);
            int h = rem / WW2;
            int w2 = rem - h * WW2;
            int dp = d - 1; if (dp < 0) dp += DD;
            int hp = h - 3; if (hp < 0) hp += HH;
            int wp = w2 - 3; if (wp < 0) wp += WW2;
            int wd = dp >> 1, nd = dp & 1;
            int wh = hp / 7, nh = hp - wh * 7;
            int ww = wp / 7, nww = wp - ww * 7;
            rowmap[tid] = ((b << 11) + wd * 256 + wh * 16 + ww) * 98 +
                          nd * 49 + nh * 7 + nww;
        }
        __syncthreads();
        const uint4* A4 = (const uint4*)g_y;
        #pragma unroll
        for (int it = 0; it < 6; it++) {
            int idx = tid + it * 256;
            int r = idx / 12, k8 = idx % 12;
            *(uint4*)(sAw + r * 52 + k8 * 4) = A4[(size_t)rowmap[r] * 12 + k8];
        }
    } else {
        const uint4* A4 = (const uint4*)(g_ao + (size_t)rowbase * 96);
        #pragma unroll
        for (int it = 0; it < 6; it++) {
            int idx = tid + it * 256;
            int r = idx / 12, k8 = idx % 12;
            *(uint4*)(sAw + r * 52 + k8 * 4) = A4[idx];
        }
    }
    {
        const uint4* s4 = (const uint4*)(g_Bp + (size_t)(EPI == 1 ? 3 : 4) * 9216);
        uint4* d4 = (uint4*)sB;
        for (int i = tid; i < 1152; i += 256) d4[i] = s4[i];
    }
    __syncthreads();

    float d[12][4];
    #pragma unroll
    for (int nt = 0; nt < 12; nt++)
        #pragma unroll
        for (int r = 0; r < 4; r++) d[nt][r] = 0.0f;
    mma6(d, sAw, sB, r0, tig, lane);

    int m0 = rowbase + r0;
    if (EPI == 1) {
        #pragma unroll
        for (int nt = 0; nt < 12; nt++) {
            int c = nt * 8 + tig * 2;
            float bx = bias[c], by = bias[c + 1];
            *(unsigned*)(g_y + (size_t)m0 * CD + c) = pack_h2(d[nt][0] + bx, d[nt][1] + by);
            *(unsigned*)(g_y + (size_t)(m0 + 8) * CD + c) = pack_h2(d[nt][2] + bx, d[nt][3] + by);
        }
    } else {
        #pragma unroll
        for (int nt = 0; nt < 12; nt++) {
            int c = nt * 8 + tig * 2;
            float bx = bias[c], by = bias[c + 1];
            #pragma unroll
            for (int rr = 0; rr < 2; rr++) {
                size_t o = (size_t)(m0 + rr * 8) * CD + c;
                float v0 = d[nt][rr * 2] + bx;
                float v1 = d[nt][rr * 2 + 1] + by;
                float g0 = 0.5f * v0 * (1.0f + erff(v0 * 0.70710678118654752f));
                float g1 = 0.5f * v1 * (1.0f + erff(v1 * 0.70710678118654752f));
                float2 rv = *(const float2*)(resid + o);
                *(float2*)(out + o) = make_float2(rv.x + g0, rv.y + g1);
            }
        }
    }
}

// ============ K3: fp16-MMA window attention ============
// smem (u32 words): q_h 2240 @0, k_h 2080 @2240, Ssh [98][60] @0 overlay, vs 2240 @5880
#define ATTN_SMEM (8120 * 4)
__global__ __launch_bounds__(224, 4)
void attn_kernel() {
    extern __shared__ unsigned smu[];
    unsigned* q_h = smu;
    unsigned* k_h = smu + 2240;
    unsigned* Ssh = smu;
    unsigned* vs = smu + 5880;

    int b_ = blockIdx.x;
    int head = blockIdx.y;
    int tid = threadIdx.x;
    int w = tid >> 5, lane = tid & 31;
    int g = lane >> 2, tig = lane & 3;
    size_t bh = (size_t)b_ * NH + head;

    {
        const uint4* q4 = (const uint4*)(g_q + bh * (NWIN * HD));
        const uint4* k4 = (const uint4*)(g_k + bh * (NWIN * HD));
        const uint4* v4 = (const uint4*)(g_v + bh * (NWIN * HD));
        for (int i4 = tid; i4 < 392; i4 += 224) {
            int n = i4 >> 2, c4 = (i4 & 3) << 2;
            *(uint4*)(q_h + n * 20 + c4) = q4[i4];
            *(uint4*)(k_h + n * 20 + c4) = k4[i4];
            *(uint4*)(vs + n * 20 + c4) = v4[i4];
        }
        for (int i = tid; i < 224; i += 224) {
            int n = 98 + (i >> 4), ww2 = i & 15;
            *(vs + n * 20 + ww2) = 0u;
        }
    }
    __syncthreads();

    int r0 = w * 16 + g;
    float d[13][4];
    #pragma unroll
    for (int nt = 0; nt < 13; nt++)
        #pragma unroll
        for (int r = 0; r < 4; r++) d[nt][r] = 0.0f;
    {
        unsigned a[2][4];
        #pragma unroll
        for (int kt = 0; kt < 2; kt++) {
            a[kt][0] = q_h[r0 * 20 + kt * 8 + tig];
            a[kt][1] = q_h[(r0 + 8) * 20 + kt * 8 + tig];
            a[kt][2] = q_h[r0 * 20 + kt * 8 + tig + 4];
            a[kt][3] = q_h[(r0 + 8) * 20 + kt * 8 + tig + 4];
        }
        #pragma unroll
        for (int nt = 0; nt < 13; nt++) {
            #pragma unroll
            for (int kt = 0; kt < 2; kt++) {
                unsigned b0 = k_h[(nt * 8 + g) * 20 + kt * 8 + tig];
                unsigned b1 = k_h[(nt * 8 + g) * 20 + kt * 8 + tig + 4];
                mma_f16(d[nt], a[kt][0], a[kt][1], a[kt][2], a[kt][3], b0, b1);
            }
        }
    }
    __syncthreads();

    bool v0 = r0 < 98, v1 = (r0 + 8) < 98;
    {
        int widx = b_ & (NWX - 1);
        int cls = (((widx >> 8) == 7) << 2) | ((((widx >> 4) & 15) == 15) << 1) |
                  ((widx & 15) == 15);
        const unsigned* bmp = (const unsigned*)(g_bm + (size_t)(cls * NH + head) * (NWIN * NWIN));
        float s0 = 0.0f, s1 = 0.0f;
        #pragma unroll
        for (int nt = 0; nt < 13; nt++) {
            int c0 = nt * 8 + tig * 2;
            float e0 = 0.f, e1 = 0.f, e2 = 0.f, e3 = 0.f;
            if (c0 < 98) {
                if (v0) {
                    unsigned bw = __ldg(bmp + r0 * 49 + (c0 >> 1));
                    float2 bb = __half22float2(*(__half2*)&bw);
                    e0 = __expf(d[nt][0] + bb.x);
                    e1 = __expf(d[nt][1] + bb.y);
                }
                if (v1) {
                    unsigned bw = __ldg(bmp + (r0 + 8) * 49 + (c0 >> 1));
                    float2 bb = __half22float2(*(__half2*)&bw);
                    e2 = __expf(d[nt][2] + bb.x);
                    e3 = __expf(d[nt][3] + bb.y);
                }
            }
            d[nt][0] = e0; d[nt][1] = e1; d[nt][2] = e2; d[nt][3] = e3;
            s0 += e0 + e1; s1 += e2 + e3;
        }
        s0 += __shfl_xor_sync(0xffffffffu, s0, 1);
        s0 += __shfl_xor_sync(0xffffffffu, s0, 2);
        s1 += __shfl_xor_sync(0xffffffffu, s1, 1);
        s1 += __shfl_xor_sync(0xffffffffu, s1, 2);
        float i0 = v0 ? (1.0f / s0) : 0.0f;
        float i1 = v1 ? (1.0f / s1) : 0.0f;
        #pragma unroll
        for (int nt = 0; nt < 13; nt++) {
            if (v0) Ssh[r0 * 60 + nt * 4 + tig] = pack_h2(d[nt][0] * i0, d[nt][1] * i0);
            if (v1) Ssh[(r0 + 8) * 60 + nt * 4 + tig] = pack_h2(d[nt][2] * i1, d[nt][3] * i1);
        }
        for (int i = tid; i < 392; i += 224)
            Ssh[(i >> 2) * 60 + 52 + (i & 3)] = 0u;
    }
    __syncthreads();

    {
        int rA = v0 ? r0 : 0;
        int rB = v1 ? (r0 + 8) : 0;
        unsigned mA = v0 ? 0xffffffffu : 0u;
        unsigned mB = v1 ? 0xffffffffu : 0u;
        unsigned vs_addr = (unsigned)__cvta_generic_to_shared(vs);
        int sub = lane & 7, hsel = (lane >> 3) & 1, nsel = lane >> 4;
        float o[4][4];
        #pragma unroll
        for (int nt = 0; nt < 4; nt++)
            #pragma unroll
            for (int r = 0; r < 4; r++) o[nt][r] = 0.0f;
        #pragma unroll
        for (int kt = 0; kt < 7; kt++) {
            unsigned a0 = Ssh[rA * 60 + kt * 8 + tig] & mA;
            unsigned a1 = Ssh[rB * 60 + kt * 8 + tig] & mB;
            unsigned a2 = Ssh[rA * 60 + kt * 8 + tig + 4] & mA;
            unsigned a3 = Ssh[rB * 60 + kt * 8 + tig + 4] & mB;
            #pragma unroll
            for (int ntp = 0; ntp < 2; ntp++) {
                unsigned addr = vs_addr +
                    ((unsigned)((16 * kt + 8 * hsel + sub) * 40 +
                                8 * (ntp * 2 + nsel)) << 1);
                unsigned b0, b1, b2, b3;
                ldsm_x4_trans(b0, b1, b2, b3, addr);
                mma_f16(o[ntp * 2], a0, a1, a2, a3, b0, b1);
                mma_f16(o[ntp * 2 + 1], a0, a1, a2, a3, b2, b3);
            }
        }
        #pragma unroll
        for (int nt = 0; nt < 4; nt++) {
            int c = nt * 8 + tig * 2;
            if (v0)
                *(unsigned*)(g_ao + ((size_t)b_ * NWIN + r0) * CD + head * HD + c) =
                    pack_h2(o[nt][0], o[nt][1]);
            if (v1)
                *(unsigned*)(g_ao + ((size_t)b_ * NWIN + r0 + 8) * CD + head * HD + c) =
                    pack_h2(o[nt][2], o[nt][3]);
        }
    }
}

// ============ launch ============
extern "C" void kernel_launch(void* const* d_in, const int* in_sizes, int n_in,
                              void* d_out, int out_size) {
    const float* x     = (const float*)d_in[0];
    const float* mask  = (const float*)d_in[1];
    const float* n1w   = (const float*)d_in[2];
    const float* n1b   = (const float*)d_in[3];
    const float* qkvw  = (const float*)d_in[4];
    const float* qkvb  = (const float*)d_in[5];
    const float* relt  = (const float*)d_in[6];
    const float* projw = (const float*)d_in[7];
    const float* projb = (const float*)d_in[8];
    const float* fc1w  = (const float*)d_in[9];
    const float* fc1b  = (const float*)d_in[10];
    float* out = (float*)d_out;

    cudaFuncSetAttribute(attn_kernel, cudaFuncAttributeMaxDynamicSharedMemorySize, ATTN_SMEM);
    cudaFuncSetAttribute(gemm_qkv, cudaFuncAttributeMaxDynamicSharedMemorySize, GEMM_SMEM);
    cudaFuncSetAttribute(gemm_tc<1>, cudaFuncAttributeMaxDynamicSharedMemorySize, GEMM_SMEM);
    cudaFuncSetAttribute(gemm_tc<2>, cudaFuncAttributeMaxDynamicSharedMemorySize, GEMM_SMEM);

    bm_kernel<<<(8 * NH * NWIN * NWIN + 255) / 256, 256>>>(relt, mask);
    prepack_kernel<<<(5 * 9216 + 255) / 256, 256>>>(qkvw, projw, fc1w);
    gemm_qkv<<<MTOT / 128, 256, GEMM_SMEM>>>(x, n1w, n1b, qkvb);
    attn_kernel<<<dim3(BTOT, NH), 224, ATTN_SMEM>>>();
    gemm_tc<1><<<MTOT / 128, 256, GEMM_SMEM>>>(projb, nullptr, nullptr);
    gemm_tc<2><<<MTOT / 128, 256, GEMM_SMEM>>>(fc1b, x, out);
}

// round 12
// speedup vs baseline: 1.9040x; 1.0144x over previous
#include <cuda_runtime.h>
#include <cuda_fp16.h>
#include <math.h>
#include <stdint.h>

// ---- problem constants ----
#define NWIN 98
#define NH 3
#define HD 32
#define CD 96
#define DD 16
#define HH 112
#define WW2 112
#define NWX 2048
#define BATCH 2
#define BTOT (BATCH*NWX)      // 4096
#define MTOT (BTOT*NWIN)      // 401408
#define LTOT (DD*HH*WW2)      // 200704
#define SCALE 0.17677669529663689f
#define LOG2E 1.4426950408889634f

// ---- scratch (fp16 intermediates) ----
__device__ __half g_q[(size_t)BTOT*NH*NWIN*HD];   // q pre-scaled by SCALE*LOG2E
__device__ __half g_k[(size_t)BTOT*NH*NWIN*HD];
__device__ __half g_v[(size_t)BTOT*NH*NWIN*HD];
__device__ __half g_ao[(size_t)MTOT*CD];
__device__ __half g_y[(size_t)MTOT*CD];          // windowed-linear order
__device__ __half g_bm[8*NH*NWIN*NWIN];          // (bias+mask)*LOG2E, fp16
__device__ __half g_Bp[5*9216];                  // prepacked fp16 B frags

// ---- helpers ----
__device__ __forceinline__ unsigned pack_h2(float a, float b) {
    __half2 h = __floats2half2_rn(a, b);
    return *(unsigned*)&h;
}
__device__ __forceinline__ float ex2f(float x) {
    float r;
    asm("ex2.approx.ftz.f32 %0, %1;" : "=f"(r) : "f"(x));
    return r;
}
__device__ __forceinline__ void mma_f16(float* d, unsigned a0, unsigned a1,
                                        unsigned a2, unsigned a3,
                                        unsigned b0, unsigned b1) {
    asm volatile(
        "mma.sync.aligned.m16n8k16.row.col.f32.f16.f16.f32 "
        "{%0,%1,%2,%3}, {%4,%5,%6,%7}, {%8,%9}, {%0,%1,%2,%3};"
        : "+f"(d[0]), "+f"(d[1]), "+f"(d[2]), "+f"(d[3])
        : "r"(a0), "r"(a1), "r"(a2), "r"(a3), "r"(b0), "r"(b1));
}
__device__ __forceinline__ void ldsm_x4_trans(unsigned& r0, unsigned& r1,
                                              unsigned& r2, unsigned& r3,
                                              unsigned addr) {
    asm volatile("ldmatrix.sync.aligned.m8n8.x4.trans.shared.b16 {%0,%1,%2,%3}, [%4];"
        : "=r"(r0), "=r"(r1), "=r"(r2), "=r"(r3) : "r"(addr));
}

// ============ K0a: combined bias+mask table (fp16, pre-scaled by LOG2E) ============
__global__ void bm_kernel(const float* __restrict__ table,
                          const float* __restrict__ mask) {
    int idx = blockIdx.x * blockDim.x + threadIdx.x;
    if (idx >= 8 * NH * NWIN * NWIN) return;
    int cls = idx / (NH * NWIN * NWIN);
    int rem = idx % (NH * NWIN * NWIN);
    int head = rem / (NWIN * NWIN);
    int r = rem % (NWIN * NWIN);
    int n = r / NWIN, m = r % NWIN;
    int d1 = n / 49, h1 = (n % 49) / 7, w1 = n % 7;
    int d2 = m / 49, h2 = (m % 49) / 7, w2 = m % 7;
    int t = (d1 - d2 + 1) * 169 + (h1 - h2 + 6) * 13 + (w1 - w2 + 6);
    int wd = (cls & 4) ? 7 : 0;
    int wh = (cls & 2) ? 15 : 0;
    int ww = (cls & 1) ? 15 : 0;
    int widx = wd * 256 + wh * 16 + ww;
    g_bm[idx] = __float2half_rn((table[t * NH + head] +
                                 mask[(size_t)widx * (NWIN * NWIN) + r]) * LOG2E);
}

// ============ K0b: prepack weights into fp16 m16n8k16 B-fragment layout ============
__global__ void prepack_kernel(const float* __restrict__ qkvw,
                               const float* __restrict__ projw,
                               const float* __restrict__ fc1w) {
    int idx = blockIdx.x * blockDim.x + threadIdx.x;
    if (idx >= 5 * 9216) return;
    int mat = idx / 9216, rem = idx % 9216;
    int c = rem / 96, k = rem % 96;
    float v;
    if (mat < 3) v = qkvw[(size_t)(mat * 96 + c) * 96 + k];
    else if (mat == 3) v = projw[(size_t)c * 96 + k];
    else v = fc1w[(size_t)c * 96 + k];
    int nt = c >> 3, g = c & 7, kt = k >> 4, w16 = k & 15;
    int reg = w16 >> 3, tig = (w16 & 7) >> 1, lo = w16 & 1;
    int hidx = ((((nt * 6 + kt) * 32) + g * 4 + tig) * 2 + reg) * 2 + lo;
    g_Bp[mat * 9216 + hidx] = __float2half_rn(v);
}

// ============ GEMM common ============
#define GEMM_SMEM ((6656 + 4608 + 128) * 4)

__device__ __forceinline__ void mma6(float d[12][4], const unsigned* sAw,
                                     const unsigned* sB, int r0, int tig, int lane) {
    const uint2* b2 = (const uint2*)sB;
    #pragma unroll
    for (int kt = 0; kt < 6; kt++) {
        unsigned a0 = sAw[r0 * 52 + kt * 8 + tig];
        unsigned a1 = sAw[(r0 + 8) * 52 + kt * 8 + tig];
        unsigned a2 = sAw[r0 * 52 + kt * 8 + tig + 4];
        unsigned a3 = sAw[(r0 + 8) * 52 + kt * 8 + tig + 4];
        #pragma unroll
        for (int nt = 0; nt < 12; nt++) {
            uint2 bf = b2[(nt * 6 + kt) * 32 + lane];
            mma_f16(d[nt], a0, a1, a2, a3, bf.x, bf.y);
        }
    }
}

// ============ K1: fused LayerNorm + window-partition + QKV GEMM ============
__global__ __launch_bounds__(256, 3)
void gemm_qkv(const float* __restrict__ x,
              const float* __restrict__ nw,
              const float* __restrict__ nb,
              const float* __restrict__ bias) {
    extern __shared__ unsigned smu[];
    unsigned* sAw = smu;            // [128][52] words
    __half* sAh = (__half*)smu;
    unsigned* sB = smu + 6656;
    int rowbase = blockIdx.x * 128;
    int tid = threadIdx.x;
    int w = tid >> 5, lane = tid & 31;
    int g = lane >> 2, tig = lane & 3;

    float nw0 = nw[lane], nw1 = nw[lane + 32], nw2 = nw[lane + 64];
    float nb0 = nb[lane], nb1 = nb[lane + 32], nb2 = nb[lane + 64];

    // ---- phase A: gather (shift+window) + LayerNorm -> fp16 smem ----
    #pragma unroll 4
    for (int i = 0; i < 16; i++) {
        int r = w * 16 + i;
        int m = rowbase + r;
        int b_ = m / NWIN, n = m % NWIN;
        int b = b_ >> 11;
        int widx = b_ & (NWX - 1);
        int wd = widx >> 8, wh = (widx >> 4) & 15, ww = widx & 15;
        int nd = n / 49, nr = n % 49, nh2 = nr / 7, nw2i = nr % 7;
        int dp = wd * 2 + nd, hp = wh * 7 + nh2, wp = ww * 7 + nw2i;
        int d = dp + 1; if (d >= DD) d -= DD;
        int h = hp + 3; if (h >= HH) h -= HH;
        int wq = wp + 3; if (wq >= WW2) wq -= WW2;
        size_t src = ((size_t)b * LTOT + (size_t)(d * (HH * WW2) + h * WW2 + wq)) * CD;
        float v0 = x[src + lane], v1 = x[src + 32 + lane], v2 = x[src + 64 + lane];
        float s = v0 + v1 + v2;
        float ss = v0 * v0 + v1 * v1 + v2 * v2;
        #pragma unroll
        for (int o = 16; o; o >>= 1) {
            s  += __shfl_xor_sync(0xffffffffu, s, o);
            ss += __shfl_xor_sync(0xffffffffu, ss, o);
        }
        float mean = s * (1.0f / 96.0f);
        float var = ss * (1.0f / 96.0f) - mean * mean;
        float rs = rsqrtf(var + 1e-5f);
        sAh[r * 104 + lane]      = __float2half_rn((v0 - mean) * rs * nw0 + nb0);
        sAh[r * 104 + lane + 32] = __float2half_rn((v1 - mean) * rs * nw1 + nb1);
        sAh[r * 104 + lane + 64] = __float2half_rn((v2 - mean) * rs * nw2 + nb2);
    }

    int m0 = rowbase + w * 16 + g;
    int b0 = m0 / NWIN, n0 = m0 % NWIN;
    int b1 = (m0 + 8) / NWIN, n1 = (m0 + 8) % NWIN;
    int r0 = w * 16 + g;
    __syncthreads();

    for (int p = 0; p < 3; p++) {
        if (p > 0) __syncthreads();
        {
            const uint4* s4 = (const uint4*)(g_Bp + (size_t)p * 9216);
            uint4* d4 = (uint4*)sB;
            for (int i = tid; i < 1152; i += 256) d4[i] = s4[i];
        }
        __syncthreads();
        float d[12][4];
        #pragma unroll
        for (int nt = 0; nt < 12; nt++)
            #pragma unroll
            for (int r = 0; r < 4; r++) d[nt][r] = 0.0f;
        mma6(d, sAw, sB, r0, tig, lane);

        __half* dstbuf = (p == 0) ? g_q : (p == 1) ? g_k : g_v;
        float sc = (p == 0) ? (SCALE * LOG2E) : 1.0f;
        #pragma unroll
        for (int nt = 0; nt < 12; nt++) {
            int c = nt * 8 + tig * 2;
            int head = c >> 5, wd = c & 31;
            float bx = bias[p * 96 + c], by = bias[p * 96 + c + 1];
            *(unsigned*)(dstbuf + ((((size_t)b0 * NH + head) * NWIN + n0) * HD + wd)) =
                pack_h2((d[nt][0] + bx) * sc, (d[nt][1] + by) * sc);
            *(unsigned*)(dstbuf + ((((size_t)b1 * NH + head) * NWIN + n1) * HD + wd)) =
                pack_h2((d[nt][2] + bx) * sc, (d[nt][3] + by) * sc);
        }
    }
}

// ============ proj (EPI=1): linear store / fc1 (EPI=2): gather + GELU + resid ============
template<int EPI>
__global__ __launch_bounds__(256, 3)
void gemm_tc(const float* __restrict__ bias,
             const float* __restrict__ resid,
             float* __restrict__ out) {
    extern __shared__ unsigned smu[];
    unsigned* sAw = smu;
    unsigned* sB = smu + 6656;
    int* rowmap = (int*)(smu + 11264);
    int rowbase = blockIdx.x * 128;
    int tid = threadIdx.x;
    int w = tid >> 5, lane = tid & 31;
    int g = lane >> 2, tig = lane & 3;
    int r0 = w * 16 + g;

    if (EPI == 2) {
        if (tid < 128) {
            int m = rowbase + tid;
            int b = m / LTOT;
            int l = m - b * LTOT;
            int d = l / (HH * WW2);
            int rem = l - d * (HH * WW2);
            int h = rem / WW2;
            int w2 = rem - h * WW2;
            int dp = d - 1; if (dp < 0) dp += DD;
            int hp = h - 3; if (hp < 0) hp += HH;
            int wp = w2 - 3; if (wp < 0) wp += WW2;
            int wd = dp >> 1, nd = dp & 1;
            int wh = hp / 7, nh = hp - wh * 7;
            int ww = wp / 7, nww = wp - ww * 7;
            rowmap[tid] = ((b << 11) + wd * 256 + wh * 16 + ww) * 98 +
                          nd * 49 + nh * 7 + nww;
        }
        __syncthreads();
        const uint4* A4 = (const uint4*)g_y;
        #pragma unroll
        for (int it = 0; it < 6; it++) {
            int idx = tid + it * 256;
            int r = idx / 12, k8 = idx % 12;
            *(uint4*)(sAw + r * 52 + k8 * 4) = A4[(size_t)rowmap[r] * 12 + k8];
        }
    } else {
        const uint4* A4 = (const uint4*)(g_ao + (size_t)rowbase * 96);
        #pragma unroll
        for (int it = 0; it < 6; it++) {
            int idx = tid + it * 256;
            int r = idx / 12, k8 = idx % 12;
            *(uint4*)(sAw + r * 52 + k8 * 4) = A4[idx];
        }
    }
    {
        const uint4* s4 = (const uint4*)(g_Bp + (size_t)(EPI == 1 ? 3 : 4) * 9216);
        uint4* d4 = (uint4*)sB;
        for (int i = tid; i < 1152; i += 256) d4[i] = s4[i];
    }
    __syncthreads();

    float d[12][4];
    #pragma unroll
    for (int nt = 0; nt < 12; nt++)
        #pragma unroll
        for (int r = 0; r < 4; r++) d[nt][r] = 0.0f;
    mma6(d, sAw, sB, r0, tig, lane);

    int m0 = rowbase + r0;
    if (EPI == 1) {
        #pragma unroll
        for (int nt = 0; nt < 12; nt++) {
            int c = nt * 8 + tig * 2;
            float bx = bias[c], by = bias[c + 1];
            *(unsigned*)(g_y + (size_t)m0 * CD + c) = pack_h2(d[nt][0] + bx, d[nt][1] + by);
            *(unsigned*)(g_y + (size_t)(m0 + 8) * CD + c) = pack_h2(d[nt][2] + bx, d[nt][3] + by);
        }
    } else {
        #pragma unroll
        for (int nt = 0; nt < 12; nt++) {
            int c = nt * 8 + tig * 2;
            float bx = bias[c], by = bias[c + 1];
            #pragma unroll
            for (int rr = 0; rr < 2; rr++) {
                size_t o = (size_t)(m0 + rr * 8) * CD + c;
                float v0 = d[nt][rr * 2] + bx;
                float v1 = d[nt][rr * 2 + 1] + by;
                float g0 = 0.5f * v0 * (1.0f + erff(v0 * 0.70710678118654752f));
                float g1 = 0.5f * v1 * (1.0f + erff(v1 * 0.70710678118654752f));
                float2 rv = *(const float2*)(resid + o);
                *(float2*)(out + o) = make_float2(rv.x + g0, rv.y + g1);
            }
        }
    }
}

// ============ K3: fp16-MMA window attention ============
// smem (u32 words): q_h 2240 @0, k_h 2080 @2240, Ssh [98][60] @0 overlay, vs 2240 @5880
#define ATTN_SMEM (8120 * 4)
__global__ __launch_bounds__(224, 4)
void attn_kernel() {
    extern __shared__ unsigned smu[];
    unsigned* q_h = smu;
    unsigned* k_h = smu + 2240;
    unsigned* Ssh = smu;
    unsigned* vs = smu + 5880;

    int b_ = blockIdx.x;
    int head = blockIdx.y;
    int tid = threadIdx.x;
    int w = tid >> 5, lane = tid & 31;
    int g = lane >> 2, tig = lane & 3;
    size_t bh = (size_t)b_ * NH + head;

    {
        const uint4* q4 = (const uint4*)(g_q + bh * (NWIN * HD));
        const uint4* k4 = (const uint4*)(g_k + bh * (NWIN * HD));
        const uint4* v4 = (const uint4*)(g_v + bh * (NWIN * HD));
        for (int i4 = tid; i4 < 392; i4 += 224) {
            int n = i4 >> 2, c4 = (i4 & 3) << 2;
            *(uint4*)(q_h + n * 20 + c4) = q4[i4];
            *(uint4*)(k_h + n * 20 + c4) = k4[i4];
            *(uint4*)(vs + n * 20 + c4) = v4[i4];
        }
        for (int i = tid; i < 224; i += 224) {
            int n = 98 + (i >> 4), ww2 = i & 15;
            *(vs + n * 20 + ww2) = 0u;
        }
    }
    __syncthreads();

    int r0 = w * 16 + g;
    float d[13][4];
    #pragma unroll
    for (int nt = 0; nt < 13; nt++)
        #pragma unroll
        for (int r = 0; r < 4; r++) d[nt][r] = 0.0f;
    {
        unsigned a[2][4];
        #pragma unroll
        for (int kt = 0; kt < 2; kt++) {
            a[kt][0] = q_h[r0 * 20 + kt * 8 + tig];
            a[kt][1] = q_h[(r0 + 8) * 20 + kt * 8 + tig];
            a[kt][2] = q_h[r0 * 20 + kt * 8 + tig + 4];
            a[kt][3] = q_h[(r0 + 8) * 20 + kt * 8 + tig + 4];
        }
        #pragma unroll
        for (int nt = 0; nt < 13; nt++) {
            #pragma unroll
            for (int kt = 0; kt < 2; kt++) {
                unsigned b0 = k_h[(nt * 8 + g) * 20 + kt * 8 + tig];
                unsigned b1 = k_h[(nt * 8 + g) * 20 + kt * 8 + tig + 4];
                mma_f16(d[nt], a[kt][0], a[kt][1], a[kt][2], a[kt][3], b0, b1);
            }
        }
    }
    __syncthreads();

    bool v0 = r0 < 98, v1 = (r0 + 8) < 98;
    {
        int widx = b_ & (NWX - 1);
        int cls = (((widx >> 8) == 7) << 2) | ((((widx >> 4) & 15) == 15) << 1) |
                  ((widx & 15) == 15);
        const unsigned* bmp = (const unsigned*)(g_bm + (size_t)(cls * NH + head) * (NWIN * NWIN));
        float s0 = 0.0f, s1 = 0.0f;
        #pragma unroll
        for (int nt = 0; nt < 13; nt++) {
            int c0 = nt * 8 + tig * 2;
            float e0 = 0.f, e1 = 0.f, e2 = 0.f, e3 = 0.f;
            if (c0 < 98) {
                if (v0) {
                    unsigned bw = __ldg(bmp + r0 * 49 + (c0 >> 1));
                    float2 bb = __half22float2(*(__half2*)&bw);
                    e0 = ex2f(d[nt][0] + bb.x);
                    e1 = ex2f(d[nt][1] + bb.y);
                }
                if (v1) {
                    unsigned bw = __ldg(bmp + (r0 + 8) * 49 + (c0 >> 1));
                    float2 bb = __half22float2(*(__half2*)&bw);
                    e2 = ex2f(d[nt][2] + bb.x);
                    e3 = ex2f(d[nt][3] + bb.y);
                }
            }
            d[nt][0] = e0; d[nt][1] = e1; d[nt][2] = e2; d[nt][3] = e3;
            s0 += e0 + e1; s1 += e2 + e3;
        }
        s0 += __shfl_xor_sync(0xffffffffu, s0, 1);
        s0 += __shfl_xor_sync(0xffffffffu, s0, 2);
        s1 += __shfl_xor_sync(0xffffffffu, s1, 1);
        s1 += __shfl_xor_sync(0xffffffffu, s1, 2);
        float i0 = v0 ? (1.0f / s0) : 0.0f;
        float i1 = v1 ? (1.0f / s1) : 0.0f;
        #pragma unroll
        for (int nt = 0; nt < 13; nt++) {
            if (v0) Ssh[r0 * 60 + nt * 4 + tig] = pack_h2(d[nt][0] * i0, d[nt][1] * i0);
            if (v1) Ssh[(r0 + 8) * 60 + nt * 4 + tig] = pack_h2(d[nt][2] * i1, d[nt][3] * i1);
        }
        for (int i = tid; i < 392; i += 224)
            Ssh[(i >> 2) * 60 + 52 + (i & 3)] = 0u;
    }
    __syncthreads();

    {
        // no masks: invalid rows (>=98) read valid smem garbage and feed only
        // discarded outputs; V pad rows + P pad words are zeroed so valid
        // outputs never touch garbage.
        unsigned vs_addr = (unsigned)__cvta_generic_to_shared(vs);
        int sub = lane & 7, hsel = (lane >> 3) & 1, nsel = lane >> 4;
        float o[4][4];
        #pragma unroll
        for (int nt = 0; nt < 4; nt++)
            #pragma unroll
            for (int r = 0; r < 4; r++) o[nt][r] = 0.0f;
        #pragma unroll
        for (int kt = 0; kt < 7; kt++) {
            unsigned a0 = Ssh[r0 * 60 + kt * 8 + tig];
            unsigned a1 = Ssh[(r0 + 8) * 60 + kt * 8 + tig];
            unsigned a2 = Ssh[r0 * 60 + kt * 8 + tig + 4];
            unsigned a3 = Ssh[(r0 + 8) * 60 + kt * 8 + tig + 4];
            #pragma unroll
            for (int ntp = 0; ntp < 2; ntp++) {
                unsigned addr = vs_addr +
                    ((unsigned)((16 * kt + 8 * hsel + sub) * 40 +
                                8 * (ntp * 2 + nsel)) << 1);
                unsigned b0, b1, b2, b3;
                ldsm_x4_trans(b0, b1, b2, b3, addr);
                mma_f16(o[ntp * 2], a0, a1, a2, a3, b0, b1);
                mma_f16(o[ntp * 2 + 1], a0, a1, a2, a3, b2, b3);
            }
        }
        #pragma unroll
        for (int nt = 0; nt < 4; nt++) {
            int c = nt * 8 + tig * 2;
            if (v0)
                *(unsigned*)(g_ao + ((size_t)b_ * NWIN + r0) * CD + head * HD + c) =
                    pack_h2(o[nt][0], o[nt][1]);
            if (v1)
                *(unsigned*)(g_ao + ((size_t)b_ * NWIN + r0 + 8) * CD + head * HD + c) =
                    pack_h2(o[nt][2], o[nt][3]);
        }
    }
}

// ============ launch ============
extern "C" void kernel_launch(void* const* d_in, const int* in_sizes, int n_in,
                              void* d_out, int out_size) {
    const float* x     = (const float*)d_in[0];
    const float* mask  = (const float*)d_in[1];
    const float* n1w   = (const float*)d_in[2];
    const float* n1b   = (const float*)d_in[3];
    const float* qkvw  = (const float*)d_in[4];
    const float* qkvb  = (const float*)d_in[5];
    const float* relt  = (const float*)d_in[6];
    const float* projw = (const float*)d_in[7];
    const float* projb = (const float*)d_in[8];
    const float* fc1w  = (const float*)d_in[9];
    const float* fc1b  = (const float*)d_in[10];
    float* out = (float*)d_out;

    cudaFuncSetAttribute(attn_kernel, cudaFuncAttributeMaxDynamicSharedMemorySize, ATTN_SMEM);
    cudaFuncSetAttribute(gemm_qkv, cudaFuncAttributeMaxDynamicSharedMemorySize, GEMM_SMEM);
    cudaFuncSetAttribute(gemm_tc<1>, cudaFuncAttributeMaxDynamicSharedMemorySize, GEMM_SMEM);
    cudaFuncSetAttribute(gemm_tc<2>, cudaFuncAttributeMaxDynamicSharedMemorySize, GEMM_SMEM);

    bm_kernel<<<(8 * NH * NWIN * NWIN + 255) / 256, 256>>>(relt, mask);
    prepack_kernel<<<(5 * 9216 + 255) / 256, 256>>>(qkvw, projw, fc1w);
    gemm_qkv<<<MTOT / 128, 256, GEMM_SMEM>>>(x, n1w, n1b, qkvb);
    attn_kernel<<<dim3(BTOT, NH), 224, ATTN_SMEM>>>();
    gemm_tc<1><<<MTOT / 128, 256, GEMM_SMEM>>>(projb, nullptr, nullptr);
    gemm_tc<2><<<MTOT / 128, 256, GEMM_SMEM>>>(fc1b, x, out);
}

// round 13
// speedup vs baseline: 2.1678x; 1.1386x over previous
#include <cuda_runtime.h>
#include <cuda_fp16.h>
#include <math.h>
#include <stdint.h>

// ---- problem constants ----
#define NWIN 98
#define NH 3
#define HD 32
#define CD 96
#define DD 16
#define HH 112
#define WW2 112
#define NWX 2048
#define BATCH 2
#define BTOT (BATCH*NWX)      // 4096
#define MTOT (BTOT*NWIN)      // 401408
#define LTOT (DD*HH*WW2)      // 200704
#define SCALE 0.17677669529663689f
#define LOG2E 1.4426950408889634f

// ---- scratch (fp16 intermediates) ----
__device__ __half g_q[(size_t)BTOT*NH*NWIN*HD];   // q pre-scaled by SCALE*LOG2E
__device__ __half g_k[(size_t)BTOT*NH*NWIN*HD];
__device__ __half g_v[(size_t)BTOT*NH*NWIN*HD];
__device__ __half g_ao[(size_t)MTOT*CD];
__device__ __half g_y[(size_t)MTOT*CD];          // windowed-linear order
__device__ __half g_bm[8*NH*NWIN*NWIN];          // (bias+mask)*LOG2E, fp16
__device__ __half g_Bp[5*9216];                  // prepacked fp16 B frags

// ---- helpers ----
__device__ __forceinline__ unsigned pack_h2(float a, float b) {
    __half2 h = __floats2half2_rn(a, b);
    return *(unsigned*)&h;
}
__device__ __forceinline__ float ex2f(float x) {
    float r;
    asm("ex2.approx.ftz.f32 %0, %1;" : "=f"(r) : "f"(x));
    return r;
}
__device__ __forceinline__ void cp16(unsigned saddr, const void* gptr) {
    asm volatile("cp.async.cg.shared.global [%0], [%1], 16;"
        :: "r"(saddr), "l"(gptr));
}
#define CP_COMMIT() asm volatile("cp.async.commit_group;" ::: "memory")
#define CP_WAIT0()  asm volatile("cp.async.wait_group 0;" ::: "memory")
__device__ __forceinline__ void mma_f16(float* d, unsigned a0, unsigned a1,
                                        unsigned a2, unsigned a3,
                                        unsigned b0, unsigned b1) {
    asm volatile(
        "mma.sync.aligned.m16n8k16.row.col.f32.f16.f16.f32 "
        "{%0,%1,%2,%3}, {%4,%5,%6,%7}, {%8,%9}, {%0,%1,%2,%3};"
        : "+f"(d[0]), "+f"(d[1]), "+f"(d[2]), "+f"(d[3])
        : "r"(a0), "r"(a1), "r"(a2), "r"(a3), "r"(b0), "r"(b1));
}
__device__ __forceinline__ void ldsm_x4_trans(unsigned& r0, unsigned& r1,
                                              unsigned& r2, unsigned& r3,
                                              unsigned addr) {
    asm volatile("ldmatrix.sync.aligned.m8n8.x4.trans.shared.b16 {%0,%1,%2,%3}, [%4];"
        : "=r"(r0), "=r"(r1), "=r"(r2), "=r"(r3) : "r"(addr));
}

// ============ K0a: combined bias+mask table (fp16, pre-scaled by LOG2E) ============
__global__ void bm_kernel(const float* __restrict__ table,
                          const float* __restrict__ mask) {
    int idx = blockIdx.x * blockDim.x + threadIdx.x;
    if (idx >= 8 * NH * NWIN * NWIN) return;
    int cls = idx / (NH * NWIN * NWIN);
    int rem = idx % (NH * NWIN * NWIN);
    int head = rem / (NWIN * NWIN);
    int r = rem % (NWIN * NWIN);
    int n = r / NWIN, m = r % NWIN;
    int d1 = n / 49, h1 = (n % 49) / 7, w1 = n % 7;
    int d2 = m / 49, h2 = (m % 49) / 7, w2 = m % 7;
    int t = (d1 - d2 + 1) * 169 + (h1 - h2 + 6) * 13 + (w1 - w2 + 6);
    int wd = (cls & 4) ? 7 : 0;
    int wh = (cls & 2) ? 15 : 0;
    int ww = (cls & 1) ? 15 : 0;
    int widx = wd * 256 + wh * 16 + ww;
    g_bm[idx] = __float2half_rn((table[t * NH + head] +
                                 mask[(size_t)widx * (NWIN * NWIN) + r]) * LOG2E);
}

// ============ K0b: prepack weights into fp16 m16n8k16 B-fragment layout ============
__global__ void prepack_kernel(const float* __restrict__ qkvw,
                               const float* __restrict__ projw,
                               const float* __restrict__ fc1w) {
    int idx = blockIdx.x * blockDim.x + threadIdx.x;
    if (idx >= 5 * 9216) return;
    int mat = idx / 9216, rem = idx % 9216;
    int c = rem / 96, k = rem % 96;
    float v;
    if (mat < 3) v = qkvw[(size_t)(mat * 96 + c) * 96 + k];
    else if (mat == 3) v = projw[(size_t)c * 96 + k];
    else v = fc1w[(size_t)c * 96 + k];
    int nt = c >> 3, g = c & 7, kt = k >> 4, w16 = k & 15;
    int reg = w16 >> 3, tig = (w16 & 7) >> 1, lo = w16 & 1;
    int hidx = ((((nt * 6 + kt) * 32) + g * 4 + tig) * 2 + reg) * 2 + lo;
    g_Bp[mat * 9216 + hidx] = __float2half_rn(v);
}

// ============ GEMM common ============
#define QKV_SMEM ((6656 + 2 * 4608) * 4)           // sA + double-buffered sB
#define TC_SMEM  ((6656 + 4608 + 128) * 4)

__device__ __forceinline__ void mma6(float d[12][4], const unsigned* sAw,
                                     const unsigned* sB, int r0, int tig, int lane) {
    const uint2* b2 = (const uint2*)sB;
    #pragma unroll
    for (int kt = 0; kt < 6; kt++) {
        unsigned a0 = sAw[r0 * 52 + kt * 8 + tig];
        unsigned a1 = sAw[(r0 + 8) * 52 + kt * 8 + tig];
        unsigned a2 = sAw[r0 * 52 + kt * 8 + tig + 4];
        unsigned a3 = sAw[(r0 + 8) * 52 + kt * 8 + tig + 4];
        #pragma unroll
        for (int nt = 0; nt < 12; nt++) {
            uint2 bf = b2[(nt * 6 + kt) * 32 + lane];
            mma_f16(d[nt], a0, a1, a2, a3, bf.x, bf.y);
        }
    }
}

// ============ K1: fused LayerNorm + window-partition + QKV GEMM ============
__global__ __launch_bounds__(256, 3)
void gemm_qkv(const float* __restrict__ x,
              const float* __restrict__ nw,
              const float* __restrict__ nb,
              const float* __restrict__ bias) {
    extern __shared__ unsigned smu[];
    unsigned* sAw = smu;            // [128][52] words
    __half* sAh = (__half*)smu;
    unsigned* sB0 = smu + 6656;
    unsigned* sB1 = smu + 6656 + 4608;
    int rowbase = blockIdx.x * 128;
    int tid = threadIdx.x;
    int w = tid >> 5, lane = tid & 31;
    int g = lane >> 2, tig = lane & 3;

    // prefetch weight frags p=0 (overlaps LN phase)
    {
        unsigned sb0a = (unsigned)__cvta_generic_to_shared(sB0);
        const uint4* s4 = (const uint4*)g_Bp;
        for (int i = tid; i < 1152; i += 256) cp16(sb0a + i * 16, s4 + i);
        CP_COMMIT();
    }

    float nw0 = nw[lane], nw1 = nw[lane + 32], nw2 = nw[lane + 64];
    float nb0 = nb[lane], nb1 = nb[lane + 32], nb2 = nb[lane + 64];

    // ---- phase A: gather (shift+window) + LayerNorm -> fp16 smem ----
    #pragma unroll 4
    for (int i = 0; i < 16; i++) {
        int r = w * 16 + i;
        int m = rowbase + r;
        int b_ = m / NWIN, n = m % NWIN;
        int b = b_ >> 11;
        int widx = b_ & (NWX - 1);
        int wd = widx >> 8, wh = (widx >> 4) & 15, ww = widx & 15;
        int nd = n / 49, nr = n % 49, nh2 = nr / 7, nw2i = nr % 7;
        int dp = wd * 2 + nd, hp = wh * 7 + nh2, wp = ww * 7 + nw2i;
        int d = dp + 1; if (d >= DD) d -= DD;
        int h = hp + 3; if (h >= HH) h -= HH;
        int wq = wp + 3; if (wq >= WW2) wq -= WW2;
        size_t src = ((size_t)b * LTOT + (size_t)(d * (HH * WW2) + h * WW2 + wq)) * CD;
        float v0 = x[src + lane], v1 = x[src + 32 + lane], v2 = x[src + 64 + lane];
        float s = v0 + v1 + v2;
        float ss = v0 * v0 + v1 * v1 + v2 * v2;
        #pragma unroll
        for (int o = 16; o; o >>= 1) {
            s  += __shfl_xor_sync(0xffffffffu, s, o);
            ss += __shfl_xor_sync(0xffffffffu, ss, o);
        }
        float mean = s * (1.0f / 96.0f);
        float var = ss * (1.0f / 96.0f) - mean * mean;
        float rs = rsqrtf(var + 1e-5f);
        sAh[r * 104 + lane]      = __float2half_rn((v0 - mean) * rs * nw0 + nb0);
        sAh[r * 104 + lane + 32] = __float2half_rn((v1 - mean) * rs * nw1 + nb1);
        sAh[r * 104 + lane + 64] = __float2half_rn((v2 - mean) * rs * nw2 + nb2);
    }

    int m0 = rowbase + w * 16 + g;
    int b0 = m0 / NWIN, n0 = m0 % NWIN;
    int b1 = (m0 + 8) / NWIN, n1 = (m0 + 8) % NWIN;
    int r0 = w * 16 + g;
    CP_WAIT0();
    __syncthreads();

    #pragma unroll
    for (int p = 0; p < 3; p++) {
        unsigned* bufs[2] = { sB0, sB1 };
        if (p < 2) {
            // prefetch next part into the other buffer
            unsigned nba = (unsigned)__cvta_generic_to_shared(bufs[(p + 1) & 1]);
            const uint4* s4 = (const uint4*)(g_Bp + (size_t)(p + 1) * 9216);
            for (int i = tid; i < 1152; i += 256) cp16(nba + i * 16, s4 + i);
            CP_COMMIT();
        }
        float d[12][4];
        #pragma unroll
        for (int nt = 0; nt < 12; nt++)
            #pragma unroll
            for (int r = 0; r < 4; r++) d[nt][r] = 0.0f;
        mma6(d, sAw, bufs[p & 1], r0, tig, lane);

        __half* dstbuf = (p == 0) ? g_q : (p == 1) ? g_k : g_v;
        float sc = (p == 0) ? (SCALE * LOG2E) : 1.0f;
        #pragma unroll
        for (int nt = 0; nt < 12; nt++) {
            int c = nt * 8 + tig * 2;
            int head = c >> 5, wd = c & 31;
            float bx = bias[p * 96 + c], by = bias[p * 96 + c + 1];
            *(unsigned*)(dstbuf + ((((size_t)b0 * NH + head) * NWIN + n0) * HD + wd)) =
                pack_h2((d[nt][0] + bx) * sc, (d[nt][1] + by) * sc);
            *(unsigned*)(dstbuf + ((((size_t)b1 * NH + head) * NWIN + n1) * HD + wd)) =
                pack_h2((d[nt][2] + bx) * sc, (d[nt][3] + by) * sc);
        }
        if (p < 2) {
            CP_WAIT0();
            __syncthreads();   // next buffer ready; prior buffer reads complete
        }
    }
}

// ============ proj (EPI=1): linear store / fc1 (EPI=2): gather + GELU + resid ============
template<int EPI>
__global__ __launch_bounds__(256, 3)
void gemm_tc(const float* __restrict__ bias,
             const float* __restrict__ resid,
             float* __restrict__ out) {
    extern __shared__ unsigned smu[];
    unsigned* sAw = smu;
    unsigned* sB = smu + 6656;
    int* rowmap = (int*)(smu + 11264);
    int rowbase = blockIdx.x * 128;
    int tid = threadIdx.x;
    int w = tid >> 5, lane = tid & 31;
    int g = lane >> 2, tig = lane & 3;
    int r0 = w * 16 + g;
    unsigned sAa = (unsigned)__cvta_generic_to_shared(sAw);
    unsigned sBa = (unsigned)__cvta_generic_to_shared(sB);

    if (EPI == 2) {
        if (tid < 128) {
            int m = rowbase + tid;
            int b = m / LTOT;
            int l = m - b * LTOT;
            int d = l / (HH * WW2);
            int rem = l - d * (HH * WW2);
            int h = rem / WW2;
            int w2 = rem - h * WW2;
            int dp = d - 1; if (dp < 0) dp += DD;
            int hp = h - 3; if (hp < 0) hp += HH;
            int wp = w2 - 3; if (wp < 0) wp += WW2;
            int wd = dp >> 1, nd = dp & 1;
            int wh = hp / 7, nh = hp - wh * 7;
            int ww = wp / 7, nww = wp - ww * 7;
            rowmap[tid] = ((b << 11) + wd * 256 + wh * 16 + ww) * 98 +
                          nd * 49 + nh * 7 + nww;
        }
        __syncthreads();
        const uint4* A4 = (const uint4*)g_y;
        #pragma unroll
        for (int it = 0; it < 6; it++) {
            int idx = tid + it * 256;
            int r = idx / 12, k8 = idx % 12;
            cp16(sAa + (r * 52 + k8 * 4) * 4, A4 + (size_t)rowmap[r] * 12 + k8);
        }
    } else {
        const uint4* A4 = (const uint4*)(g_ao + (size_t)rowbase * 96);
        #pragma unroll
        for (int it = 0; it < 6; it++) {
            int idx = tid + it * 256;
            int r = idx / 12, k8 = idx % 12;
            cp16(sAa + (r * 52 + k8 * 4) * 4, A4 + idx);
        }
    }
    {
        const uint4* s4 = (const uint4*)(g_Bp + (size_t)(EPI == 1 ? 3 : 4) * 9216);
        for (int i = tid; i < 1152; i += 256) cp16(sBa + i * 16, s4 + i);
    }
    CP_COMMIT();
    CP_WAIT0();
    __syncthreads();

    float d[12][4];
    #pragma unroll
    for (int nt = 0; nt < 12; nt++)
        #pragma unroll
        for (int r = 0; r < 4; r++) d[nt][r] = 0.0f;
    mma6(d, sAw, sB, r0, tig, lane);

    int m0 = rowbase + r0;
    if (EPI == 1) {
        #pragma unroll
        for (int nt = 0; nt < 12; nt++) {
            int c = nt * 8 + tig * 2;
            float bx = bias[c], by = bias[c + 1];
            *(unsigned*)(g_y + (size_t)m0 * CD + c) = pack_h2(d[nt][0] + bx, d[nt][1] + by);
            *(unsigned*)(g_y + (size_t)(m0 + 8) * CD + c) = pack_h2(d[nt][2] + bx, d[nt][3] + by);
        }
    } else {
        #pragma unroll
        for (int nt = 0; nt < 12; nt++) {
            int c = nt * 8 + tig * 2;
            float bx = bias[c], by = bias[c + 1];
            #pragma unroll
            for (int rr = 0; rr < 2; rr++) {
                size_t o = (size_t)(m0 + rr * 8) * CD + c;
                float v0 = d[nt][rr * 2] + bx;
                float v1 = d[nt][rr * 2 + 1] + by;
                float g0 = 0.5f * v0 * (1.0f + erff(v0 * 0.70710678118654752f));
                float g1 = 0.5f * v1 * (1.0f + erff(v1 * 0.70710678118654752f));
                float2 rv = *(const float2*)(resid + o);
                *(float2*)(out + o) = make_float2(rv.x + g0, rv.y + g1);
            }
        }
    }
}

// ============ K3: fp16-MMA window attention ============
// smem (u32 words): q_h 2240 @0, k_h 2080 @2240, Ssh [98][60] @0 overlay, vs 2240 @5880
#define ATTN_SMEM (8120 * 4)
__global__ __launch_bounds__(224, 4)
void attn_kernel() {
    extern __shared__ unsigned smu[];
    unsigned* q_h = smu;
    unsigned* k_h = smu + 2240;
    unsigned* Ssh = smu;
    unsigned* vs = smu + 5880;

    int b_ = blockIdx.x;
    int head = blockIdx.y;
    int tid = threadIdx.x;
    int w = tid >> 5, lane = tid & 31;
    int g = lane >> 2, tig = lane & 3;
    size_t bh = (size_t)b_ * NH + head;

    // ---- cp.async loads: all q/k/v requests in flight at once ----
    {
        unsigned qa = (unsigned)__cvta_generic_to_shared(q_h);
        unsigned ka = (unsigned)__cvta_generic_to_shared(k_h);
        unsigned va = (unsigned)__cvta_generic_to_shared(vs);
        const uint4* q4 = (const uint4*)(g_q + bh * (NWIN * HD));
        const uint4* k4 = (const uint4*)(g_k + bh * (NWIN * HD));
        const uint4* v4 = (const uint4*)(g_v + bh * (NWIN * HD));
        for (int i4 = tid; i4 < 392; i4 += 224) {
            int n = i4 >> 2, c4 = (i4 & 3) << 2;
            unsigned off = (n * 20 + c4) * 4;
            cp16(qa + off, q4 + i4);
            cp16(ka + off, k4 + i4);
            cp16(va + off, v4 + i4);
        }
        CP_COMMIT();
        // zero vs pad rows 98..111 (independent region)
        for (int i = tid; i < 224; i += 224) {
            int n = 98 + (i >> 4), ww2 = i & 15;
            *(vs + n * 20 + ww2) = 0u;
        }
        CP_WAIT0();
    }
    __syncthreads();

    int r0 = w * 16 + g;
    float d[13][4];
    #pragma unroll
    for (int nt = 0; nt < 13; nt++)
        #pragma unroll
        for (int r = 0; r < 4; r++) d[nt][r] = 0.0f;
    {
        unsigned a[2][4];
        #pragma unroll
        for (int kt = 0; kt < 2; kt++) {
            a[kt][0] = q_h[r0 * 20 + kt * 8 + tig];
            a[kt][1] = q_h[(r0 + 8) * 20 + kt * 8 + tig];
            a[kt][2] = q_h[r0 * 20 + kt * 8 + tig + 4];
            a[kt][3] = q_h[(r0 + 8) * 20 + kt * 8 + tig + 4];
        }
        #pragma unroll
        for (int nt = 0; nt < 13; nt++) {
            #pragma unroll
            for (int kt = 0; kt < 2; kt++) {
                unsigned b0 = k_h[(nt * 8 + g) * 20 + kt * 8 + tig];
                unsigned b1 = k_h[(nt * 8 + g) * 20 + kt * 8 + tig + 4];
                mma_f16(d[nt], a[kt][0], a[kt][1], a[kt][2], a[kt][3], b0, b1);
            }
        }
    }
    __syncthreads();

    bool v0 = r0 < 98, v1 = (r0 + 8) < 98;
    {
        int widx = b_ & (NWX - 1);
        int cls = (((widx >> 8) == 7) << 2) | ((((widx >> 4) & 15) == 15) << 1) |
                  ((widx & 15) == 15);
        const unsigned* bmp = (const unsigned*)(g_bm + (size_t)(cls * NH + head) * (NWIN * NWIN));
        float s0 = 0.0f, s1 = 0.0f;
        #pragma unroll
        for (int nt = 0; nt < 13; nt++) {
            int c0 = nt * 8 + tig * 2;
            float e0 = 0.f, e1 = 0.f, e2 = 0.f, e3 = 0.f;
            if (c0 < 98) {
                if (v0) {
                    unsigned bw = __ldg(bmp + r0 * 49 + (c0 >> 1));
                    float2 bb = __half22float2(*(__half2*)&bw);
                    e0 = ex2f(d[nt][0] + bb.x);
                    e1 = ex2f(d[nt][1] + bb.y);
                }
                if (v1) {
                    unsigned bw = __ldg(bmp + (r0 + 8) * 49 + (c0 >> 1));
                    float2 bb = __half22float2(*(__half2*)&bw);
                    e2 = ex2f(d[nt][2] + bb.x);
                    e3 = ex2f(d[nt][3] + bb.y);
                }
            }
            d[nt][0] = e0; d[nt][1] = e1; d[nt][2] = e2; d[nt][3] = e3;
            s0 += e0 + e1; s1 += e2 + e3;
        }
        s0 += __shfl_xor_sync(0xffffffffu, s0, 1);
        s0 += __shfl_xor_sync(0xffffffffu, s0, 2);
        s1 += __shfl_xor_sync(0xffffffffu, s1, 1);
        s1 += __shfl_xor_sync(0xffffffffu, s1, 2);
        float i0 = v0 ? (1.0f / s0) : 0.0f;
        float i1 = v1 ? (1.0f / s1) : 0.0f;
        #pragma unroll
        for (int nt = 0; nt < 13; nt++) {
            if (v0) Ssh[r0 * 60 + nt * 4 + tig] = pack_h2(d[nt][0] * i0, d[nt][1] * i0);
            if (v1) Ssh[(r0 + 8) * 60 + nt * 4 + tig] = pack_h2(d[nt][2] * i1, d[nt][3] * i1);
        }
        for (int i = tid; i < 392; i += 224)
            Ssh[(i >> 2) * 60 + 52 + (i & 3)] = 0u;
    }
    __syncthreads();

    {
        unsigned vs_addr = (unsigned)__cvta_generic_to_shared(vs);
        int sub = lane & 7, hsel = (lane >> 3) & 1, nsel = lane >> 4;
        float o[4][4];
        #pragma unroll
        for (int nt = 0; nt < 4; nt++)
            #pragma unroll
            for (int r = 0; r < 4; r++) o[nt][r] = 0.0f;
        #pragma unroll
        for (int kt = 0; kt < 7; kt++) {
            unsigned a0 = Ssh[r0 * 60 + kt * 8 + tig];
            unsigned a1 = Ssh[(r0 + 8) * 60 + kt * 8 + tig];
            unsigned a2 = Ssh[r0 * 60 + kt * 8 + tig + 4];
            unsigned a3 = Ssh[(r0 + 8) * 60 + kt * 8 + tig + 4];
            #pragma unroll
            for (int ntp = 0; ntp < 2; ntp++) {
                unsigned addr = vs_addr +
                    ((unsigned)((16 * kt + 8 * hsel + sub) * 40 +
                                8 * (ntp * 2 + nsel)) << 1);
                unsigned b0, b1, b2, b3;
                ldsm_x4_trans(b0, b1, b2, b3, addr);
                mma_f16(o[ntp * 2], a0, a1, a2, a3, b0, b1);
                mma_f16(o[ntp * 2 + 1], a0, a1, a2, a3, b2, b3);
            }
        }
        #pragma unroll
        for (int nt = 0; nt < 4; nt++) {
            int c = nt * 8 + tig * 2;
            if (v0)
                *(unsigned*)(g_ao + ((size_t)b_ * NWIN + r0) * CD + head * HD + c) =
                    pack_h2(o[nt][0], o[nt][1]);
            if (v1)
                *(unsigned*)(g_ao + ((size_t)b_ * NWIN + r0 + 8) * CD + head * HD + c) =
                    pack_h2(o[nt][2], o[nt][3]);
        }
    }
}

// ============ launch ============
extern "C" void kernel_launch(void* const* d_in, const int* in_sizes, int n_in,
                              void* d_out, int out_size) {
    const float* x     = (const float*)d_in[0];
    const float* mask  = (const float*)d_in[1];
    const float* n1w   = (const float*)d_in[2];
    const float* n1b   = (const float*)d_in[3];
    const float* qkvw  = (const float*)d_in[4];
    const float* qkvb  = (const float*)d_in[5];
    const float* relt  = (const float*)d_in[6];
    const float* projw = (const float*)d_in[7];
    const float* projb = (const float*)d_in[8];
    const float* fc1w  = (const float*)d_in[9];
    const float* fc1b  = (const float*)d_in[10];
    float* out = (float*)d_out;

    cudaFuncSetAttribute(attn_kernel, cudaFuncAttributeMaxDynamicSharedMemorySize, ATTN_SMEM);
    cudaFuncSetAttribute(gemm_qkv, cudaFuncAttributeMaxDynamicSharedMemorySize, QKV_SMEM);
    cudaFuncSetAttribute(gemm_tc<1>, cudaFuncAttributeMaxDynamicSharedMemorySize, TC_SMEM);
    cudaFuncSetAttribute(gemm_tc<2>, cudaFuncAttributeMaxDynamicSharedMemorySize, TC_SMEM);

    bm_kernel<<<(8 * NH * NWIN * NWIN + 255) / 256, 256>>>(relt, mask);
    prepack_kernel<<<(5 * 9216 + 255) / 256, 256>>>(qkvw, projw, fc1w);
    gemm_qkv<<<MTOT / 128, 256, QKV_SMEM>>>(x, n1w, n1b, qkvb);
    attn_kernel<<<dim3(BTOT, NH), 224, ATTN_SMEM>>>();
    gemm_tc<1><<<MTOT / 128, 256, TC_SMEM>>>(projb, nullptr, nullptr);
    gemm_tc<2><<<MTOT / 128, 256, TC_SMEM>>>(fc1b, x, out);
}

// round 14
// speedup vs baseline: 2.2596x; 1.0423x over previous
#include <cuda_runtime.h>
#include <cuda_fp16.h>
#include <math.h>
#include <stdint.h>

// ---- problem constants ----
#define NWIN 98
#define NH 3
#define HD 32
#define CD 96
#define DD 16
#define HH 112
#define WW2 112
#define NWX 2048
#define BATCH 2
#define BTOT (BATCH*NWX)      // 4096
#define MTOT (BTOT*NWIN)      // 401408
#define LTOT (DD*HH*WW2)      // 200704
#define SCALE 0.17677669529663689f
#define LOG2E 1.4426950408889634f

// ---- scratch (fp16 intermediates) ----
__device__ __half g_q[(size_t)BTOT*NH*NWIN*HD];   // q pre-scaled by SCALE*LOG2E
__device__ __half g_k[(size_t)BTOT*NH*NWIN*HD];
__device__ __half g_v[(size_t)BTOT*NH*NWIN*HD];
__device__ __half g_ao[(size_t)MTOT*CD];
__device__ __half g_y[(size_t)MTOT*CD];          // windowed-linear order
__device__ __half g_bm[8*NH*NWIN*NWIN];          // (bias+mask)*LOG2E, fp16
__device__ __half g_Bp[5*9216];                  // prepacked fp16 B frags

// ---- helpers ----
__device__ __forceinline__ unsigned pack_h2(float a, float b) {
    __half2 h = __floats2half2_rn(a, b);
    return *(unsigned*)&h;
}
__device__ __forceinline__ float ex2f(float x) {
    float r;
    asm("ex2.approx.ftz.f32 %0, %1;" : "=f"(r) : "f"(x));
    return r;
}
__device__ __forceinline__ void cp16(unsigned saddr, const void* gptr) {
    asm volatile("cp.async.cg.shared.global [%0], [%1], 16;"
        :: "r"(saddr), "l"(gptr));
}
#define CP_COMMIT() asm volatile("cp.async.commit_group;" ::: "memory")
#define CP_WAIT0()  asm volatile("cp.async.wait_group 0;" ::: "memory")
__device__ __forceinline__ void mma_f16(float* d, unsigned a0, unsigned a1,
                                        unsigned a2, unsigned a3,
                                        unsigned b0, unsigned b1) {
    asm volatile(
        "mma.sync.aligned.m16n8k16.row.col.f32.f16.f16.f32 "
        "{%0,%1,%2,%3}, {%4,%5,%6,%7}, {%8,%9}, {%0,%1,%2,%3};"
        : "+f"(d[0]), "+f"(d[1]), "+f"(d[2]), "+f"(d[3])
        : "r"(a0), "r"(a1), "r"(a2), "r"(a3), "r"(b0), "r"(b1));
}
__device__ __forceinline__ void ldsm_x4_trans(unsigned& r0, unsigned& r1,
                                              unsigned& r2, unsigned& r3,
                                              unsigned addr) {
    asm volatile("ldmatrix.sync.aligned.m8n8.x4.trans.shared.b16 {%0,%1,%2,%3}, [%4];"
        : "=r"(r0), "=r"(r1), "=r"(r2), "=r"(r3) : "r"(addr));
}

// ============ K0: bias+mask table (fp16, *LOG2E) + weight prepack, one launch ============
#define BM_TOTAL (8 * NH * NWIN * NWIN)
__global__ void init_kernel(const float* __restrict__ table,
                            const float* __restrict__ mask,
                            const float* __restrict__ qkvw,
                            const float* __restrict__ projw,
                            const float* __restrict__ fc1w) {
    int idx = blockIdx.x * blockDim.x + threadIdx.x;
    if (idx < BM_TOTAL) {
        int cls = idx / (NH * NWIN * NWIN);
        int rem = idx % (NH * NWIN * NWIN);
        int head = rem / (NWIN * NWIN);
        int r = rem % (NWIN * NWIN);
        int n = r / NWIN, m = r % NWIN;
        int d1 = n / 49, h1 = (n % 49) / 7, w1 = n % 7;
        int d2 = m / 49, h2 = (m % 49) / 7, w2 = m % 7;
        int t = (d1 - d2 + 1) * 169 + (h1 - h2 + 6) * 13 + (w1 - w2 + 6);
        int wd = (cls & 4) ? 7 : 0;
        int wh = (cls & 2) ? 15 : 0;
        int ww = (cls & 1) ? 15 : 0;
        int widx = wd * 256 + wh * 16 + ww;
        g_bm[idx] = __float2half_rn((table[t * NH + head] +
                                     mask[(size_t)widx * (NWIN * NWIN) + r]) * LOG2E);
    } else if (idx < BM_TOTAL + 5 * 9216) {
        int p = idx - BM_TOTAL;
        int mat = p / 9216, rem = p % 9216;
        int c = rem / 96, k = rem % 96;
        float v;
        if (mat < 3) v = qkvw[(size_t)(mat * 96 + c) * 96 + k];
        else if (mat == 3) v = projw[(size_t)c * 96 + k];
        else v = fc1w[(size_t)c * 96 + k];
        int nt = c >> 3, g = c & 7, kt = k >> 4, w16 = k & 15;
        int reg = w16 >> 3, tig = (w16 & 7) >> 1, lo = w16 & 1;
        int hidx = ((((nt * 6 + kt) * 32) + g * 4 + tig) * 2 + reg) * 2 + lo;
        g_Bp[mat * 9216 + hidx] = __float2half_rn(v);
    }
}

// ============ GEMM common ============
#define QKV_SMEM ((6656 + 2 * 4608) * 4)
#define TC_SMEM  ((6656 + 4608 + 128) * 4)

__device__ __forceinline__ void mma6(float d[12][4], const unsigned* sAw,
                                     const unsigned* sB, int r0, int tig, int lane) {
    const uint2* b2 = (const uint2*)sB;
    #pragma unroll
    for (int kt = 0; kt < 6; kt++) {
        unsigned a0 = sAw[r0 * 52 + kt * 8 + tig];
        unsigned a1 = sAw[(r0 + 8) * 52 + kt * 8 + tig];
        unsigned a2 = sAw[r0 * 52 + kt * 8 + tig + 4];
        unsigned a3 = sAw[(r0 + 8) * 52 + kt * 8 + tig + 4];
        #pragma unroll
        for (int nt = 0; nt < 12; nt++) {
            uint2 bf = b2[(nt * 6 + kt) * 32 + lane];
            mma_f16(d[nt], a0, a1, a2, a3, bf.x, bf.y);
        }
    }
}

// ============ K1: fused LayerNorm + window-partition + QKV GEMM ============
__global__ __launch_bounds__(256, 3)
void gemm_qkv(const float* __restrict__ x,
              const float* __restrict__ nw,
              const float* __restrict__ nb,
              const float* __restrict__ bias) {
    extern __shared__ unsigned smu[];
    unsigned* sAw = smu;            // [128][52] words
    __half* sAh = (__half*)smu;
    unsigned* sB0 = smu + 6656;
    unsigned* sB1 = smu + 6656 + 4608;
    int rowbase = blockIdx.x * 128;
    int tid = threadIdx.x;
    int w = tid >> 5, lane = tid & 31;
    int g = lane >> 2, tig = lane & 3;

    {
        unsigned sb0a = (unsigned)__cvta_generic_to_shared(sB0);
        const uint4* s4 = (const uint4*)g_Bp;
        for (int i = tid; i < 1152; i += 256) cp16(sb0a + i * 16, s4 + i);
        CP_COMMIT();
    }

    float nw0 = nw[lane], nw1 = nw[lane + 32], nw2 = nw[lane + 64];
    float nb0 = nb[lane], nb1 = nb[lane + 32], nb2 = nb[lane + 64];

    #pragma unroll 4
    for (int i = 0; i < 16; i++) {
        int r = w * 16 + i;
        int m = rowbase + r;
        int b_ = m / NWIN, n = m % NWIN;
        int b = b_ >> 11;
        int widx = b_ & (NWX - 1);
        int wd = widx >> 8, wh = (widx >> 4) & 15, ww = widx & 15;
        int nd = n / 49, nr = n % 49, nh2 = nr / 7, nw2i = nr % 7;
        int dp = wd * 2 + nd, hp = wh * 7 + nh2, wp = ww * 7 + nw2i;
        int d = dp + 1; if (d >= DD) d -= DD;
        int h = hp + 3; if (h >= HH) h -= HH;
        int wq = wp + 3; if (wq >= WW2) wq -= WW2;
        size_t src = ((size_t)b * LTOT + (size_t)(d * (HH * WW2) + h * WW2 + wq)) * CD;
        float v0 = x[src + lane], v1 = x[src + 32 + lane], v2 = x[src + 64 + lane];
        float s = v0 + v1 + v2;
        float ss = v0 * v0 + v1 * v1 + v2 * v2;
        #pragma unroll
        for (int o = 16; o; o >>= 1) {
            s  += __shfl_xor_sync(0xffffffffu, s, o);
            ss += __shfl_xor_sync(0xffffffffu, ss, o);
        }
        float mean = s * (1.0f / 96.0f);
        float var = ss * (1.0f / 96.0f) - mean * mean;
        float rs = rsqrtf(var + 1e-5f);
        sAh[r * 104 + lane]      = __float2half_rn((v0 - mean) * rs * nw0 + nb0);
        sAh[r * 104 + lane + 32] = __float2half_rn((v1 - mean) * rs * nw1 + nb1);
        sAh[r * 104 + lane + 64] = __float2half_rn((v2 - mean) * rs * nw2 + nb2);
    }

    int m0 = rowbase + w * 16 + g;
    int b0 = m0 / NWIN, n0 = m0 % NWIN;
    int b1 = (m0 + 8) / NWIN, n1 = (m0 + 8) % NWIN;
    int r0 = w * 16 + g;
    CP_WAIT0();
    __syncthreads();

    #pragma unroll
    for (int p = 0; p < 3; p++) {
        unsigned* bufs[2] = { sB0, sB1 };
        if (p < 2) {
            unsigned nba = (unsigned)__cvta_generic_to_shared(bufs[(p + 1) & 1]);
            const uint4* s4 = (const uint4*)(g_Bp + (size_t)(p + 1) * 9216);
            for (int i = tid; i < 1152; i += 256) cp16(nba + i * 16, s4 + i);
            CP_COMMIT();
        }
        float d[12][4];
        #pragma unroll
        for (int nt = 0; nt < 12; nt++)
            #pragma unroll
            for (int r = 0; r < 4; r++) d[nt][r] = 0.0f;
        mma6(d, sAw, bufs[p & 1], r0, tig, lane);

        __half* dstbuf = (p == 0) ? g_q : (p == 1) ? g_k : g_v;
        float sc = (p == 0) ? (SCALE * LOG2E) : 1.0f;
        #pragma unroll
        for (int nt = 0; nt < 12; nt++) {
            int c = nt * 8 + tig * 2;
            int head = c >> 5, wd = c & 31;
            float bx = bias[p * 96 + c], by = bias[p * 96 + c + 1];
            *(unsigned*)(dstbuf + ((((size_t)b0 * NH + head) * NWIN + n0) * HD + wd)) =
                pack_h2((d[nt][0] + bx) * sc, (d[nt][1] + by) * sc);
            *(unsigned*)(dstbuf + ((((size_t)b1 * NH + head) * NWIN + n1) * HD + wd)) =
                pack_h2((d[nt][2] + bx) * sc, (d[nt][3] + by) * sc);
        }
        if (p < 2) {
            CP_WAIT0();
            __syncthreads();
        }
    }
}

// ============ proj (EPI=1): linear store / fc1 (EPI=2): gather + GELU + resid ============
template<int EPI>
__global__ __launch_bounds__(256, 3)
void gemm_tc(const float* __restrict__ bias,
             const float* __restrict__ resid,
             float* __restrict__ out) {
    extern __shared__ unsigned smu[];
    unsigned* sAw = smu;
    unsigned* sB = smu + 6656;
    int* rowmap = (int*)(smu + 11264);
    int rowbase = blockIdx.x * 128;
    int tid = threadIdx.x;
    int w = tid >> 5, lane = tid & 31;
    int g = lane >> 2, tig = lane & 3;
    int r0 = w * 16 + g;
    unsigned sAa = (unsigned)__cvta_generic_to_shared(sAw);
    unsigned sBa = (unsigned)__cvta_generic_to_shared(sB);

    if (EPI == 2) {
        if (tid < 128) {
            int m = rowbase + tid;
            int b = m / LTOT;
            int l = m - b * LTOT;
            int d = l / (HH * WW2);
            int rem = l - d * (HH * WW2);
            int h = rem / WW2;
            int w2 = rem - h * WW2;
            int dp = d - 1; if (dp < 0) dp += DD;
            int hp = h - 3; if (hp < 0) hp += HH;
            int wp = w2 - 3; if (wp < 0) wp += WW2;
            int wd = dp >> 1, nd = dp & 1;
            int wh = hp / 7, nh = hp - wh * 7;
            int ww = wp / 7, nww = wp - ww * 7;
            rowmap[tid] = ((b << 11) + wd * 256 + wh * 16 + ww) * 98 +
                          nd * 49 + nh * 7 + nww;
        }
        __syncthreads();
        const uint4* A4 = (const uint4*)g_y;
        #pragma unroll
        for (int it = 0; it < 6; it++) {
            int idx = tid + it * 256;
            int r = idx / 12, k8 = idx % 12;
            cp16(sAa + (r * 52 + k8 * 4) * 4, A4 + (size_t)rowmap[r] * 12 + k8);
        }
    } else {
        const uint4* A4 = (const uint4*)(g_ao + (size_t)rowbase * 96);
        #pragma unroll
        for (int it = 0; it < 6; it++) {
            int idx = tid + it * 256;
            int r = idx / 12, k8 = idx % 12;
            cp16(sAa + (r * 52 + k8 * 4) * 4, A4 + idx);
        }
    }
    {
        const uint4* s4 = (const uint4*)(g_Bp + (size_t)(EPI == 1 ? 3 : 4) * 9216);
        for (int i = tid; i < 1152; i += 256) cp16(sBa + i * 16, s4 + i);
    }
    CP_COMMIT();
    CP_WAIT0();
    __syncthreads();

    float d[12][4];
    #pragma unroll
    for (int nt = 0; nt < 12; nt++)
        #pragma unroll
        for (int r = 0; r < 4; r++) d[nt][r] = 0.0f;
    mma6(d, sAw, sB, r0, tig, lane);

    int m0 = rowbase + r0;
    if (EPI == 1) {
        #pragma unroll
        for (int nt = 0; nt < 12; nt++) {
            int c = nt * 8 + tig * 2;
            float bx = bias[c], by = bias[c + 1];
            *(unsigned*)(g_y + (size_t)m0 * CD + c) = pack_h2(d[nt][0] + bx, d[nt][1] + by);
            *(unsigned*)(g_y + (size_t)(m0 + 8) * CD + c) = pack_h2(d[nt][2] + bx, d[nt][3] + by);
        }
    } else {
        #pragma unroll
        for (int nt = 0; nt < 12; nt++) {
            int c = nt * 8 + tig * 2;
            float bx = bias[c], by = bias[c + 1];
            #pragma unroll
            for (int rr = 0; rr < 2; rr++) {
                size_t o = (size_t)(m0 + rr * 8) * CD + c;
                float v0 = d[nt][rr * 2] + bx;
                float v1 = d[nt][rr * 2 + 1] + by;
                float g0 = 0.5f * v0 * (1.0f + erff(v0 * 0.70710678118654752f));
                float g1 = 0.5f * v1 * (1.0f + erff(v1 * 0.70710678118654752f));
                float2 rv = *(const float2*)(resid + o);
                *(float2*)(out + o) = make_float2(rv.x + g0, rv.y + g1);
            }
        }
    }
}

// ============ K3: fp16-MMA window attention — single barrier ============
// smem (u32 words): q_h [112][20] 2240 @0, k_h [104][20] 2080 @2240,
//                   vs [112][20] 2240 @4320, Ssh [112][60] 6720 @6560
// total 13280 words = 53120 B -> 4 CTAs/SM
#define ATTN_SMEM (13280 * 4)
__global__ __launch_bounds__(224, 4)
void attn_kernel() {
    extern __shared__ unsigned smu[];
    unsigned* q_h = smu;
    unsigned* k_h = smu + 2240;
    unsigned* vs = smu + 4320;
    unsigned* Ssh = smu + 6560;

    int b_ = blockIdx.x;
    int head = blockIdx.y;
    int tid = threadIdx.x;
    int w = tid >> 5, lane = tid & 31;
    int g = lane >> 2, tig = lane & 3;
    size_t bh = (size_t)b_ * NH + head;

    // ---- cp.async loads ----
    {
        unsigned qa = (unsigned)__cvta_generic_to_shared(q_h);
        unsigned ka = (unsigned)__cvta_generic_to_shared(k_h);
        unsigned va = (unsigned)__cvta_generic_to_shared(vs);
        const uint4* q4 = (const uint4*)(g_q + bh * (NWIN * HD));
        const uint4* k4 = (const uint4*)(g_k + bh * (NWIN * HD));
        const uint4* v4 = (const uint4*)(g_v + bh * (NWIN * HD));
        for (int i4 = tid; i4 < 392; i4 += 224) {
            int n = i4 >> 2, c4 = (i4 & 3) << 2;
            unsigned off = (n * 20 + c4) * 4;
            cp16(qa + off, q4 + i4);
            cp16(ka + off, k4 + i4);
            cp16(va + off, v4 + i4);
        }
        CP_COMMIT();
        // zero vs pad rows 98..111
        {
            int n = 98 + (tid >> 4), ww2 = tid & 15;
            vs[n * 20 + ww2] = 0u;
        }
        CP_WAIT0();
    }
    __syncthreads();   // the ONLY block barrier

    int r0 = w * 16 + g;
    // ---- S = Q K^T ----
    float d[13][4];
    #pragma unroll
    for (int nt = 0; nt < 13; nt++)
        #pragma unroll
        for (int r = 0; r < 4; r++) d[nt][r] = 0.0f;
    {
        unsigned a[2][4];
        #pragma unroll
        for (int kt = 0; kt < 2; kt++) {
            a[kt][0] = q_h[r0 * 20 + kt * 8 + tig];
            a[kt][1] = q_h[(r0 + 8) * 20 + kt * 8 + tig];
            a[kt][2] = q_h[r0 * 20 + kt * 8 + tig + 4];
            a[kt][3] = q_h[(r0 + 8) * 20 + kt * 8 + tig + 4];
        }
        #pragma unroll
        for (int nt = 0; nt < 13; nt++) {
            #pragma unroll
            for (int kt = 0; kt < 2; kt++) {
                unsigned b0 = k_h[(nt * 8 + g) * 20 + kt * 8 + tig];
                unsigned b1 = k_h[(nt * 8 + g) * 20 + kt * 8 + tig + 4];
                mma_f16(d[nt], a[kt][0], a[kt][1], a[kt][2], a[kt][3], b0, b1);
            }
        }
    }

    bool v0 = r0 < 98, v1 = (r0 + 8) < 98;
    // ---- softmax (thread-private through smem; garbage rows feed discarded outputs) ----
    {
        int widx = b_ & (NWX - 1);
        int cls = (((widx >> 8) == 7) << 2) | ((((widx >> 4) & 15) == 15) << 1) |
                  ((widx & 15) == 15);
        const unsigned* bmp = (const unsigned*)(g_bm + (size_t)(cls * NH + head) * (NWIN * NWIN));
        float s0 = 0.0f, s1 = 0.0f;
        #pragma unroll
        for (int nt = 0; nt < 13; nt++) {
            int c0 = nt * 8 + tig * 2;
            float e0 = 0.f, e1 = 0.f, e2 = 0.f, e3 = 0.f;
            if (c0 < 98) {
                unsigned bw0 = __ldg(bmp + r0 * 49 + (c0 >> 1));
                float2 bb0 = __half22float2(*(__half2*)&bw0);
                e0 = ex2f(d[nt][0] + bb0.x);
                e1 = ex2f(d[nt][1] + bb0.y);
                unsigned bw1 = __ldg(bmp + (r0 + 8) * 49 + (c0 >> 1));
                float2 bb1 = __half22float2(*(__half2*)&bw1);
                e2 = ex2f(d[nt][2] + bb1.x);
                e3 = ex2f(d[nt][3] + bb1.y);
            }
            d[nt][0] = e0; d[nt][1] = e1; d[nt][2] = e2; d[nt][3] = e3;
            s0 += e0 + e1; s1 += e2 + e3;
        }
        s0 += __shfl_xor_sync(0xffffffffu, s0, 1);
        s0 += __shfl_xor_sync(0xffffffffu, s0, 2);
        s1 += __shfl_xor_sync(0xffffffffu, s1, 1);
        s1 += __shfl_xor_sync(0xffffffffu, s1, 2);
        float i0 = 1.0f / s0;
        float i1 = 1.0f / s1;
        #pragma unroll
        for (int nt = 0; nt < 13; nt++) {
            Ssh[r0 * 60 + nt * 4 + tig] = pack_h2(d[nt][0] * i0, d[nt][1] * i0);
            Ssh[(r0 + 8) * 60 + nt * 4 + tig] = pack_h2(d[nt][2] * i1, d[nt][3] * i1);
        }
        // zero own pad words (k-chunk 6 tail reads)
        Ssh[r0 * 60 + 52 + tig] = 0u;
        Ssh[(r0 + 8) * 60 + 52 + tig] = 0u;
    }
    // no barrier: PV reads only this thread's Ssh rows + vs (barriered at load)

    // ---- O = P V ----
    {
        unsigned vs_addr = (unsigned)__cvta_generic_to_shared(vs);
        int sub = lane & 7, hsel = (lane >> 3) & 1, nsel = lane >> 4;
        float o[4][4];
        #pragma unroll
        for (int nt = 0; nt < 4; nt++)
            #pragma unroll
            for (int r = 0; r < 4; r++) o[nt][r] = 0.0f;
        #pragma unroll
        for (int kt = 0; kt < 7; kt++) {
            unsigned a0 = Ssh[r0 * 60 + kt * 8 + tig];
            unsigned a1 = Ssh[(r0 + 8) * 60 + kt * 8 + tig];
            unsigned a2 = Ssh[r0 * 60 + kt * 8 + tig + 4];
            unsigned a3 = Ssh[(r0 + 8) * 60 + kt * 8 + tig + 4];
            #pragma unroll
            for (int ntp = 0; ntp < 2; ntp++) {
                unsigned addr = vs_addr +
                    ((unsigned)((16 * kt + 8 * hsel + sub) * 40 +
                                8 * (ntp * 2 + nsel)) << 1);
                unsigned b0, b1, b2, b3;
                ldsm_x4_trans(b0, b1, b2, b3, addr);
                mma_f16(o[ntp * 2], a0, a1, a2, a3, b0, b1);
                mma_f16(o[ntp * 2 + 1], a0, a1, a2, a3, b2, b3);
            }
        }
        #pragma unroll
        for (int nt = 0; nt < 4; nt++) {
            int c = nt * 8 + tig * 2;
            if (v0)
                *(unsigned*)(g_ao + ((size_t)b_ * NWIN + r0) * CD + head * HD + c) =
                    pack_h2(o[nt][0], o[nt][1]);
            if (v1)
                *(unsigned*)(g_ao + ((size_t)b_ * NWIN + r0 + 8) * CD + head * HD + c) =
                    pack_h2(o[nt][2], o[nt][3]);
        }
    }
}

// ============ launch ============
extern "C" void kernel_launch(void* const* d_in, const int* in_sizes, int n_in,
                              void* d_out, int out_size) {
    const float* x     = (const float*)d_in[0];
    const float* mask  = (const float*)d_in[1];
    const float* n1w   = (const float*)d_in[2];
    const float* n1b   = (const float*)d_in[3];
    const float* qkvw  = (const float*)d_in[4];
    const float* qkvb  = (const float*)d_in[5];
    const float* relt  = (const float*)d_in[6];
    const float* projw = (const float*)d_in[7];
    const float* projb = (const float*)d_in[8];
    const float* fc1w  = (const float*)d_in[9];
    const float* fc1b  = (const float*)d_in[10];
    float* out = (float*)d_out;

    cudaFuncSetAttribute(attn_kernel, cudaFuncAttributeMaxDynamicSharedMemorySize, ATTN_SMEM);
    cudaFuncSetAttribute(gemm_qkv, cudaFuncAttributeMaxDynamicSharedMemorySize, QKV_SMEM);
    cudaFuncSetAttribute(gemm_tc<1>, cudaFuncAttributeMaxDynamicSharedMemorySize, TC_SMEM);
    cudaFuncSetAttribute(gemm_tc<2>, cudaFuncAttributeMaxDynamicSharedMemorySize, TC_SMEM);

    init_kernel<<<(BM_TOTAL + 5 * 9216 + 255) / 256, 256>>>(relt, mask, qkvw, projw, fc1w);
    gemm_qkv<<<MTOT / 128, 256, QKV_SMEM>>>(x, n1w, n1b, qkvb);
    attn_kernel<<<dim3(BTOT, NH), 224, ATTN_SMEM>>>();
    gemm_tc<1><<<MTOT / 128, 256, TC_SMEM>>>(projb, nullptr, nullptr);
    gemm_tc<2><<<MTOT / 128, 256, TC_SMEM>>>(fc1b, x, out);
}

// round 15
// speedup vs baseline: 2.4323x; 1.0764x over previous
#include <cuda_runtime.h>
#include <cuda_fp16.h>
#include <math.h>
#include <stdint.h>

// ---- problem constants ----
#define NWIN 98
#define NH 3
#define HD 32
#define CD 96
#define DD 16
#define HH 112
#define WW2 112
#define NWX 2048
#define BATCH 2
#define BTOT (BATCH*NWX)      // 4096
#define MTOT (BTOT*NWIN)      // 401408
#define LTOT (DD*HH*WW2)      // 200704
#define SCALE 0.17677669529663689f
#define LOG2E 1.4426950408889634f

// ---- scratch (fp16 intermediates) ----
__device__ __half g_q[(size_t)BTOT*NH*NWIN*HD];   // q pre-scaled by SCALE*LOG2E
__device__ __half g_k[(size_t)BTOT*NH*NWIN*HD];
__device__ __half g_v[(size_t)BTOT*NH*NWIN*HD];
__device__ __half g_ao[(size_t)MTOT*CD];
__device__ __half g_y[(size_t)MTOT*CD];          // windowed-linear order
__device__ __half g_bm[8*NH*NWIN*NWIN];          // (bias+mask)*LOG2E, fp16
__device__ __half g_Bp[5*9216];                  // prepacked fp16 B frags

// ---- helpers ----
__device__ __forceinline__ unsigned pack_h2(float a, float b) {
    __half2 h = __floats2half2_rn(a, b);
    return *(unsigned*)&h;
}
__device__ __forceinline__ float ex2f(float x) {
    float r;
    asm("ex2.approx.ftz.f32 %0, %1;" : "=f"(r) : "f"(x));
    return r;
}
__device__ __forceinline__ void cp16(unsigned saddr, const void* gptr) {
    asm volatile("cp.async.cg.shared.global [%0], [%1], 16;"
        :: "r"(saddr), "l"(gptr));
}
#define CP_COMMIT() asm volatile("cp.async.commit_group;" ::: "memory")
#define CP_WAIT0()  asm volatile("cp.async.wait_group 0;" ::: "memory")
__device__ __forceinline__ void mma_f16(float* d, unsigned a0, unsigned a1,
                                        unsigned a2, unsigned a3,
                                        unsigned b0, unsigned b1) {
    asm volatile(
        "mma.sync.aligned.m16n8k16.row.col.f32.f16.f16.f32 "
        "{%0,%1,%2,%3}, {%4,%5,%6,%7}, {%8,%9}, {%0,%1,%2,%3};"
        : "+f"(d[0]), "+f"(d[1]), "+f"(d[2]), "+f"(d[3])
        : "r"(a0), "r"(a1), "r"(a2), "r"(a3), "r"(b0), "r"(b1));
}
__device__ __forceinline__ void ldsm_x4_trans(unsigned& r0, unsigned& r1,
                                              unsigned& r2, unsigned& r3,
                                              unsigned addr) {
    asm volatile("ldmatrix.sync.aligned.m8n8.x4.trans.shared.b16 {%0,%1,%2,%3}, [%4];"
        : "=r"(r0), "=r"(r1), "=r"(r2), "=r"(r3) : "r"(addr));
}

// ============ K0: bias+mask table + weight prepack ============
#define BM_TOTAL (8 * NH * NWIN * NWIN)
__global__ void init_kernel(const float* __restrict__ table,
                            const float* __restrict__ mask,
                            const float* __restrict__ qkvw,
                            const float* __restrict__ projw,
                            const float* __restrict__ fc1w) {
    int idx = blockIdx.x * blockDim.x + threadIdx.x;
    if (idx < BM_TOTAL) {
        int cls = idx / (NH * NWIN * NWIN);
        int rem = idx % (NH * NWIN * NWIN);
        int head = rem / (NWIN * NWIN);
        int r = rem % (NWIN * NWIN);
        int n = r / NWIN, m = r % NWIN;
        int d1 = n / 49, h1 = (n % 49) / 7, w1 = n % 7;
        int d2 = m / 49, h2 = (m % 49) / 7, w2 = m % 7;
        int t = (d1 - d2 + 1) * 169 + (h1 - h2 + 6) * 13 + (w1 - w2 + 6);
        int wd = (cls & 4) ? 7 : 0;
        int wh = (cls & 2) ? 15 : 0;
        int ww = (cls & 1) ? 15 : 0;
        int widx = wd * 256 + wh * 16 + ww;
        g_bm[idx] = __float2half_rn((table[t * NH + head] +
                                     mask[(size_t)widx * (NWIN * NWIN) + r]) * LOG2E);
    } else if (idx < BM_TOTAL + 5 * 9216) {
        int p = idx - BM_TOTAL;
        int mat = p / 9216, rem = p % 9216;
        int c = rem / 96, k = rem % 96;
        float v;
        if (mat < 3) v = qkvw[(size_t)(mat * 96 + c) * 96 + k];
        else if (mat == 3) v = projw[(size_t)c * 96 + k];
        else v = fc1w[(size_t)c * 96 + k];
        int nt = c >> 3, g = c & 7, kt = k >> 4, w16 = k & 15;
        int reg = w16 >> 3, tig = (w16 & 7) >> 1, lo = w16 & 1;
        int hidx = ((((nt * 6 + kt) * 32) + g * 4 + tig) * 2 + reg) * 2 + lo;
        g_Bp[mat * 9216 + hidx] = __float2half_rn(v);
    }
}

// ============ GEMM common ============
#define QKV_SMEM ((6656 + 2 * 4608) * 4)
#define TC_SMEM  ((6656 + 4608 + 128) * 4)

__device__ __forceinline__ void mma6(float d[12][4], const unsigned* sAw,
                                     const unsigned* sB, int r0, int tig, int lane) {
    const uint2* b2 = (const uint2*)sB;
    #pragma unroll
    for (int kt = 0; kt < 6; kt++) {
        unsigned a0 = sAw[r0 * 52 + kt * 8 + tig];
        unsigned a1 = sAw[(r0 + 8) * 52 + kt * 8 + tig];
        unsigned a2 = sAw[r0 * 52 + kt * 8 + tig + 4];
        unsigned a3 = sAw[(r0 + 8) * 52 + kt * 8 + tig + 4];
        #pragma unroll
        for (int nt = 0; nt < 12; nt++) {
            uint2 bf = b2[(nt * 6 + kt) * 32 + lane];
            mma_f16(d[nt], a0, a1, a2, a3, bf.x, bf.y);
        }
    }
}

// ============ K1: fused LayerNorm + window-partition + QKV GEMM ============
__global__ __launch_bounds__(256, 3)
void gemm_qkv(const float* __restrict__ x,
              const float* __restrict__ nw,
              const float* __restrict__ nb,
              const float* __restrict__ bias) {
    extern __shared__ unsigned smu[];
    unsigned* sAw = smu;            // [128][52] words
    __half* sAh = (__half*)smu;
    unsigned* sB0 = smu + 6656;
    unsigned* sB1 = smu + 6656 + 4608;
    int rowbase = blockIdx.x * 128;
    int tid = threadIdx.x;
    int w = tid >> 5, lane = tid & 31;
    int g = lane >> 2, tig = lane & 3;

    {
        unsigned sb0a = (unsigned)__cvta_generic_to_shared(sB0);
        const uint4* s4 = (const uint4*)g_Bp;
        for (int i = tid; i < 1152; i += 256) cp16(sb0a + i * 16, s4 + i);
        CP_COMMIT();
    }

    float nw0 = nw[lane], nw1 = nw[lane + 32], nw2 = nw[lane + 64];
    float nb0 = nb[lane], nb1 = nb[lane + 32], nb2 = nb[lane + 64];

    #pragma unroll 4
    for (int i = 0; i < 16; i++) {
        int r = w * 16 + i;
        int m = rowbase + r;
        int b_ = m / NWIN, n = m % NWIN;
        int b = b_ >> 11;
        int widx = b_ & (NWX - 1);
        int wd = widx >> 8, wh = (widx >> 4) & 15, ww = widx & 15;
        int nd = n / 49, nr = n % 49, nh2 = nr / 7, nw2i = nr % 7;
        int dp = wd * 2 + nd, hp = wh * 7 + nh2, wp = ww * 7 + nw2i;
        int d = dp + 1; if (d >= DD) d -= DD;
        int h = hp + 3; if (h >= HH) h -= HH;
        int wq = wp + 3; if (wq >= WW2) wq -= WW2;
        size_t src = ((size_t)b * LTOT + (size_t)(d * (HH * WW2) + h * WW2 + wq)) * CD;
        float v0 = x[src + lane], v1 = x[src + 32 + lane], v2 = x[src + 64 + lane];
        float s = v0 + v1 + v2;
        float ss = v0 * v0 + v1 * v1 + v2 * v2;
        #pragma unroll
        for (int o = 16; o; o >>= 1) {
            s  += __shfl_xor_sync(0xffffffffu, s, o);
            ss += __shfl_xor_sync(0xffffffffu, ss, o);
        }
        float mean = s * (1.0f / 96.0f);
        float var = ss * (1.0f / 96.0f) - mean * mean;
        float rs = rsqrtf(var + 1e-5f);
        sAh[r * 104 + lane]      = __float2half_rn((v0 - mean) * rs * nw0 + nb0);
        sAh[r * 104 + lane + 32] = __float2half_rn((v1 - mean) * rs * nw1 + nb1);
        sAh[r * 104 + lane + 64] = __float2half_rn((v2 - mean) * rs * nw2 + nb2);
    }

    int m0 = rowbase + w * 16 + g;
    int b0 = m0 / NWIN, n0 = m0 % NWIN;
    int b1 = (m0 + 8) / NWIN, n1 = (m0 + 8) % NWIN;
    int r0 = w * 16 + g;
    CP_WAIT0();
    __syncthreads();

    #pragma unroll
    for (int p = 0; p < 3; p++) {
        unsigned* bufs[2] = { sB0, sB1 };
        if (p < 2) {
            unsigned nba = (unsigned)__cvta_generic_to_shared(bufs[(p + 1) & 1]);
            const uint4* s4 = (const uint4*)(g_Bp + (size_t)(p + 1) * 9216);
            for (int i = tid; i < 1152; i += 256) cp16(nba + i * 16, s4 + i);
            CP_COMMIT();
        }
        float d[12][4];
        #pragma unroll
        for (int nt = 0; nt < 12; nt++)
            #pragma unroll
            for (int r = 0; r < 4; r++) d[nt][r] = 0.0f;
        mma6(d, sAw, bufs[p & 1], r0, tig, lane);

        __half* dstbuf = (p == 0) ? g_q : (p == 1) ? g_k : g_v;
        float sc = (p == 0) ? (SCALE * LOG2E) : 1.0f;
        #pragma unroll
        for (int nt = 0; nt < 12; nt++) {
            int c = nt * 8 + tig * 2;
            int head = c >> 5, wd = c & 31;
            float bx = bias[p * 96 + c], by = bias[p * 96 + c + 1];
            *(unsigned*)(dstbuf + ((((size_t)b0 * NH + head) * NWIN + n0) * HD + wd)) =
                pack_h2((d[nt][0] + bx) * sc, (d[nt][1] + by) * sc);
            *(unsigned*)(dstbuf + ((((size_t)b1 * NH + head) * NWIN + n1) * HD + wd)) =
                pack_h2((d[nt][2] + bx) * sc, (d[nt][3] + by) * sc);
        }
        if (p < 2) {
            CP_WAIT0();
            __syncthreads();
        }
    }
}

// ============ proj (EPI=1): linear store / fc1 (EPI=2): gather + GELU + resid ============
template<int EPI>
__global__ __launch_bounds__(256, 3)
void gemm_tc(const float* __restrict__ bias,
             const float* __restrict__ resid,
             float* __restrict__ out) {
    extern __shared__ unsigned smu[];
    unsigned* sAw = smu;
    unsigned* sB = smu + 6656;
    int* rowmap = (int*)(smu + 11264);
    int rowbase = blockIdx.x * 128;
    int tid = threadIdx.x;
    int w = tid >> 5, lane = tid & 31;
    int g = lane >> 2, tig = lane & 3;
    int r0 = w * 16 + g;
    unsigned sAa = (unsigned)__cvta_generic_to_shared(sAw);
    unsigned sBa = (unsigned)__cvta_generic_to_shared(sB);

    if (EPI == 2) {
        if (tid < 128) {
            int m = rowbase + tid;
            int b = m / LTOT;
            int l = m - b * LTOT;
            int d = l / (HH * WW2);
            int rem = l - d * (HH * WW2);
            int h = rem / WW2;
            int w2 = rem - h * WW2;
            int dp = d - 1; if (dp < 0) dp += DD;
            int hp = h - 3; if (hp < 0) hp += HH;
            int wp = w2 - 3; if (wp < 0) wp += WW2;
            int wd = dp >> 1, nd = dp & 1;
            int wh = hp / 7, nh = hp - wh * 7;
            int ww = wp / 7, nww = wp - ww * 7;
            rowmap[tid] = ((b << 11) + wd * 256 + wh * 16 + ww) * 98 +
                          nd * 49 + nh * 7 + nww;
        }
        __syncthreads();
        const uint4* A4 = (const uint4*)g_y;
        #pragma unroll
        for (int it = 0; it < 6; it++) {
            int idx = tid + it * 256;
            int r = idx / 12, k8 = idx % 12;
            cp16(sAa + (r * 52 + k8 * 4) * 4, A4 + (size_t)rowmap[r] * 12 + k8);
        }
    } else {
        const uint4* A4 = (const uint4*)(g_ao + (size_t)rowbase * 96);
        #pragma unroll
        for (int it = 0; it < 6; it++) {
            int idx = tid + it * 256;
            int r = idx / 12, k8 = idx % 12;
            cp16(sAa + (r * 52 + k8 * 4) * 4, A4 + idx);
        }
    }
    {
        const uint4* s4 = (const uint4*)(g_Bp + (size_t)(EPI == 1 ? 3 : 4) * 9216);
        for (int i = tid; i < 1152; i += 256) cp16(sBa + i * 16, s4 + i);
    }
    CP_COMMIT();
    CP_WAIT0();
    __syncthreads();

    float d[12][4];
    #pragma unroll
    for (int nt = 0; nt < 12; nt++)
        #pragma unroll
        for (int r = 0; r < 4; r++) d[nt][r] = 0.0f;
    mma6(d, sAw, sB, r0, tig, lane);

    int m0 = rowbase + r0;
    if (EPI == 1) {
        #pragma unroll
        for (int nt = 0; nt < 12; nt++) {
            int c = nt * 8 + tig * 2;
            float bx = bias[c], by = bias[c + 1];
            *(unsigned*)(g_y + (size_t)m0 * CD + c) = pack_h2(d[nt][0] + bx, d[nt][1] + by);
            *(unsigned*)(g_y + (size_t)(m0 + 8) * CD + c) = pack_h2(d[nt][2] + bx, d[nt][3] + by);
        }
    } else {
        #pragma unroll
        for (int nt = 0; nt < 12; nt++) {
            int c = nt * 8 + tig * 2;
            float bx = bias[c], by = bias[c + 1];
            #pragma unroll
            for (int rr = 0; rr < 2; rr++) {
                size_t o = (size_t)(m0 + rr * 8) * CD + c;
                float v0 = d[nt][rr * 2] + bx;
                float v1 = d[nt][rr * 2 + 1] + by;
                float g0 = 0.5f * v0 * (1.0f + erff(v0 * 0.70710678118654752f));
                float g1 = 0.5f * v1 * (1.0f + erff(v1 * 0.70710678118654752f));
                float2 rv = *(const float2*)(resid + o);
                *(float2*)(out + o) = make_float2(rv.x + g0, rv.y + g1);
            }
        }
    }
}

// ============ K3: fp16-MMA window attention — register-resident P ============
// smem (u32 words): q_h [112][20] 2240 @0, k_h [104][20] 2080 @2240,
//                   vs [112][20] 2240 @4320  -> 6560 words = 26240 B
#define ATTN_SMEM (6560 * 4)
__global__ __launch_bounds__(224, 4)
void attn_kernel() {
    extern __shared__ unsigned smu[];
    unsigned* q_h = smu;
    unsigned* k_h = smu + 2240;
    unsigned* vs = smu + 4320;

    int b_ = blockIdx.x;
    int head = blockIdx.y;
    int tid = threadIdx.x;
    int w = tid >> 5, lane = tid & 31;
    int g = lane >> 2, tig = lane & 3;
    size_t bh = (size_t)b_ * NH + head;

    // ---- cp.async loads ----
    {
        unsigned qa = (unsigned)__cvta_generic_to_shared(q_h);
        unsigned ka = (unsigned)__cvta_generic_to_shared(k_h);
        unsigned va = (unsigned)__cvta_generic_to_shared(vs);
        const uint4* q4 = (const uint4*)(g_q + bh * (NWIN * HD));
        const uint4* k4 = (const uint4*)(g_k + bh * (NWIN * HD));
        const uint4* v4 = (const uint4*)(g_v + bh * (NWIN * HD));
        for (int i4 = tid; i4 < 392; i4 += 224) {
            int n = i4 >> 2, c4 = (i4 & 3) << 2;
            unsigned off = (n * 20 + c4) * 4;
            cp16(qa + off, q4 + i4);
            cp16(ka + off, k4 + i4);
            cp16(va + off, v4 + i4);
        }
        CP_COMMIT();
        // zero vs pad rows 98..111 (PV reads them via ldmatrix)
        {
            int n = 98 + (tid >> 4), ww2 = tid & 15;
            vs[n * 20 + ww2] = 0u;
        }
        CP_WAIT0();
    }
    __syncthreads();   // the ONLY block barrier

    int r0 = w * 16 + g;
    // ---- S = Q K^T ----
    float d[13][4];
    #pragma unroll
    for (int nt = 0; nt < 13; nt++)
        #pragma unroll
        for (int r = 0; r < 4; r++) d[nt][r] = 0.0f;
    {
        unsigned a[2][4];
        #pragma unroll
        for (int kt = 0; kt < 2; kt++) {
            a[kt][0] = q_h[r0 * 20 + kt * 8 + tig];
            a[kt][1] = q_h[(r0 + 8) * 20 + kt * 8 + tig];
            a[kt][2] = q_h[r0 * 20 + kt * 8 + tig + 4];
            a[kt][3] = q_h[(r0 + 8) * 20 + kt * 8 + tig + 4];
        }
        #pragma unroll
        for (int nt = 0; nt < 13; nt++) {
            #pragma unroll
            for (int kt = 0; kt < 2; kt++) {
                unsigned b0 = k_h[(nt * 8 + g) * 20 + kt * 8 + tig];
                unsigned b1 = k_h[(nt * 8 + g) * 20 + kt * 8 + tig + 4];
                mma_f16(d[nt], a[kt][0], a[kt][1], a[kt][2], a[kt][3], b0, b1);
            }
        }
    }

    bool v0 = r0 < 98, v1 = (r0 + 8) < 98;
    // ---- softmax in registers; pack P directly as PV A-fragments ----
    unsigned pa[13][2];
    {
        int widx = b_ & (NWX - 1);
        int cls = (((widx >> 8) == 7) << 2) | ((((widx >> 4) & 15) == 15) << 1) |
                  ((widx & 15) == 15);
        const unsigned* bmp = (const unsigned*)(g_bm + (size_t)(cls * NH + head) * (NWIN * NWIN));
        float s0 = 0.0f, s1 = 0.0f;
        #pragma unroll
        for (int nt = 0; nt < 13; nt++) {
            int c0 = nt * 8 + tig * 2;
            float e0 = 0.f, e1 = 0.f, e2 = 0.f, e3 = 0.f;
            if (c0 < 98) {
                unsigned bw0 = __ldg(bmp + r0 * 49 + (c0 >> 1));
                float2 bb0 = __half22float2(*(__half2*)&bw0);
                e0 = ex2f(d[nt][0] + bb0.x);
                e1 = ex2f(d[nt][1] + bb0.y);
                unsigned bw1 = __ldg(bmp + (r0 + 8) * 49 + (c0 >> 1));
                float2 bb1 = __half22float2(*(__half2*)&bw1);
                e2 = ex2f(d[nt][2] + bb1.x);
                e3 = ex2f(d[nt][3] + bb1.y);
            }
            d[nt][0] = e0; d[nt][1] = e1; d[nt][2] = e2; d[nt][3] = e3;
            s0 += e0 + e1; s1 += e2 + e3;
        }
        s0 += __shfl_xor_sync(0xffffffffu, s0, 1);
        s0 += __shfl_xor_sync(0xffffffffu, s0, 2);
        s1 += __shfl_xor_sync(0xffffffffu, s1, 1);
        s1 += __shfl_xor_sync(0xffffffffu, s1, 2);
        float i0 = 1.0f / s0;
        float i1 = 1.0f / s1;
        #pragma unroll
        for (int nt = 0; nt < 13; nt++) {
            pa[nt][0] = pack_h2(d[nt][0] * i0, d[nt][1] * i0);   // rows r0
            pa[nt][1] = pack_h2(d[nt][2] * i1, d[nt][3] * i1);   // rows r0+8
        }
    }

    // ---- O = P V : P A-frags straight from registers ----
    {
        unsigned vs_addr = (unsigned)__cvta_generic_to_shared(vs);
        int sub = lane & 7, hsel = (lane >> 3) & 1, nsel = lane >> 4;
        float o[4][4];
        #pragma unroll
        for (int nt = 0; nt < 4; nt++)
            #pragma unroll
            for (int r = 0; r < 4; r++) o[nt][r] = 0.0f;
        #pragma unroll
        for (int kt = 0; kt < 7; kt++) {
            unsigned a0 = pa[2 * kt][0];
            unsigned a1 = pa[2 * kt][1];
            unsigned a2 = (kt < 6) ? pa[2 * kt + 1][0] : 0u;
            unsigned a3 = (kt < 6) ? pa[2 * kt + 1][1] : 0u;
            #pragma unroll
            for (int ntp = 0; ntp < 2; ntp++) {
                unsigned addr = vs_addr +
                    ((unsigned)((16 * kt + 8 * hsel + sub) * 40 +
                                8 * (ntp * 2 + nsel)) << 1);
                unsigned b0, b1, b2, b3;
                ldsm_x4_trans(b0, b1, b2, b3, addr);
                mma_f16(o[ntp * 2], a0, a1, a2, a3, b0, b1);
                mma_f16(o[ntp * 2 + 1], a0, a1, a2, a3, b2, b3);
            }
        }
        #pragma unroll
        for (int nt = 0; nt < 4; nt++) {
            int c = nt * 8 + tig * 2;
            if (v0)
                *(unsigned*)(g_ao + ((size_t)b_ * NWIN + r0) * CD + head * HD + c) =
                    pack_h2(o[nt][0], o[nt][1]);
            if (v1)
                *(unsigned*)(g_ao + ((size_t)b_ * NWIN + r0 + 8) * CD + head * HD + c) =
                    pack_h2(o[nt][2], o[nt][3]);
        }
    }
}

// ============ launch ============
extern "C" void kernel_launch(void* const* d_in, const int* in_sizes, int n_in,
                              void* d_out, int out_size) {
    const float* x     = (const float*)d_in[0];
    const float* mask  = (const float*)d_in[1];
    const float* n1w   = (const float*)d_in[2];
    const float* n1b   = (const float*)d_in[3];
    const float* qkvw  = (const float*)d_in[4];
    const float* qkvb  = (const float*)d_in[5];
    const float* relt  = (const float*)d_in[6];
    const float* projw = (const float*)d_in[7];
    const float* projb = (const float*)d_in[8];
    const float* fc1w  = (const float*)d_in[9];
    const float* fc1b  = (const float*)d_in[10];
    float* out = (float*)d_out;

    cudaFuncSetAttribute(attn_kernel, cudaFuncAttributeMaxDynamicSharedMemorySize, ATTN_SMEM);
    cudaFuncSetAttribute(gemm_qkv, cudaFuncAttributeMaxDynamicSharedMemorySize, QKV_SMEM);
    cudaFuncSetAttribute(gemm_tc<1>, cudaFuncAttributeMaxDynamicSharedMemorySize, TC_SMEM);
    cudaFuncSetAttribute(gemm_tc<2>, cudaFuncAttributeMaxDynamicSharedMemorySize, TC_SMEM);

    init_kernel<<<(BM_TOTAL + 5 * 9216 + 255) / 256, 256>>>(relt, mask, qkvw, projw, fc1w);
    gemm_qkv<<<MTOT / 128, 256, QKV_SMEM>>>(x, n1w, n1b, qkvb);
    attn_kernel<<<dim3(BTOT, NH), 224, ATTN_SMEM>>>();
    gemm_tc<1><<<MTOT / 128, 256, TC_SMEM>>>(projb, nullptr, nullptr);
    gemm_tc<2><<<MTOT / 128, 256, TC_SMEM>>>(fc1b, x, out);
}